// round 13
// baseline (speedup 1.0000x reference)
#include <cuda_runtime.h>
#include <cuda_bf16.h>

#define Bb 4
#define Cc 64
#define NN 4096    // 64*64 merged positions
#define HH 128
#define WW 128
#define LOG2E 1.4426950408889634f

// -------- scratch (static device globals) --------
__device__ float    g_c1[Bb*NN*Cc];        // (B,N,64)
__device__ unsigned g_qw [Bb*NN*32];       // q*log2e bf16x2 words (ch pairs, natural order)
__device__ unsigned g_kw [Bb*NN*32];       // k bf16x2 words (ch pairs, pair-permuted)
__device__ unsigned g_vtw[Bb*64*(NN/2)];   // v bf16x2 [b][ch][pos-pair], pair-permuted per 64-tile
__device__ float    g_o1p[4*Bb*NN*Cc];     // split-KV unnormalized partial O
__device__ float    g_ml [4*Bb*NN*2];      // split-KV per-row (m, l), m in log2 units
__device__ float    g_y  [Bb*NN*Cc];       // pre-upsample output
__device__ float    g_spart[64*Bb*64*64];  // channel-attn partial scores per pos-tile
__device__ float    g_s2 [Bb*64*64];       // reduced channel-attn scores
__device__ float    g_M  [Bb*64*64];       // w1_right @ softmax(scores)

__device__ __forceinline__ unsigned pk2(float lo, float hi) {
    __nv_bfloat162 h = __floats2bfloat162_rn(lo, hi);
    return *reinterpret_cast<unsigned*>(&h);
}
__device__ __forceinline__ int permw(int w) {
    return (w & ~7) | ((w & 3) << 1) | ((w >> 2) & 1);
}
__device__ __forceinline__ float ex2(float x) {
    float r;
    asm("ex2.approx.f32 %0, %1;" : "=f"(r) : "f"(x));
    return r;
}

// =====================================================================
// K1: fused patch-merge + LayerNorm + pm linear (256->64)
// grid (hh=64, b=4), block 256
// =====================================================================
extern __shared__ float smM[];
__global__ void k_merge_pml(const float* __restrict__ x,
                            const float* __restrict__ gamma,
                            const float* __restrict__ beta,
                            const float* __restrict__ pm_w,
                            const float* __restrict__ pm_b) {
    float (*ts)[65] = (float(*)[65])smM;              // [256][65]
    float (*Ws)[65] = (float(*)[65])(smM + 256 * 65); // [64][65]
    __shared__ float s_mu[64], s_rs[64];
    int b = blockIdx.y, hh = blockIdx.x, tid = threadIdx.x;

    for (int e = tid; e < 8192; e += 256) {
        int c2 = e >> 6;
        int p  = e & 63;
        int dr = c2 >> 6;
        int ch = c2 & 63;
        float2 v = *(const float2*)&x[(((b * 64 + ch) * 128) + 2 * hh + dr) * 128 + 2 * p];
        ts[dr * 64 + ch][p]       = v.x;
        ts[dr * 64 + ch + 128][p] = v.y;
    }
    __syncthreads();

    int w = tid >> 5, lane = tid & 31;
    for (int p = w * 8; p < w * 8 + 8; p++) {
        float s = 0.f, ss = 0.f;
        for (int c = lane; c < 256; c += 32) {
            float v = ts[c][p];
            s += v; ss += v * v;
        }
        #pragma unroll
        for (int off = 16; off; off >>= 1) {
            s  += __shfl_xor_sync(0xffffffffu, s,  off);
            ss += __shfl_xor_sync(0xffffffffu, ss, off);
        }
        float mu  = s * (1.f / 256.f);
        float var = ss * (1.f / 256.f) - mu * mu;
        if (lane == 0) { s_mu[p] = mu; s_rs[p] = rsqrtf(var + 1e-5f); }
    }
    __syncthreads();

    for (int e = tid; e < 16384; e += 256) {
        int c = e >> 6, p = e & 63;
        ts[c][p] = (ts[c][p] - s_mu[p]) * s_rs[p] * gamma[c] + beta[c];
    }

    int tx = tid & 15, ty = tid >> 4;
    float acc[4][4] = {};
    for (int kc = 0; kc < 4; kc++) {
        __syncthreads();
        int cg = tid & 15, r0 = tid >> 4;
        for (int rr = r0; rr < 64; rr += 16) {
            float4 wv = *(const float4*)&pm_w[rr * 256 + kc * 64 + cg * 4];
            Ws[rr][cg * 4 + 0] = wv.x; Ws[rr][cg * 4 + 1] = wv.y;
            Ws[rr][cg * 4 + 2] = wv.z; Ws[rr][cg * 4 + 3] = wv.w;
        }
        __syncthreads();
        #pragma unroll 8
        for (int c = 0; c < 64; c++) {
            float a[4], wv[4];
            #pragma unroll
            for (int i = 0; i < 4; i++) a[i]  = ts[kc * 64 + c][ty * 4 + i];
            #pragma unroll
            for (int j = 0; j < 4; j++) wv[j] = Ws[tx * 4 + j][c];
            #pragma unroll
            for (int i = 0; i < 4; i++)
                #pragma unroll
                for (int j = 0; j < 4; j++)
                    acc[i][j] += a[i] * wv[j];
        }
    }
    #pragma unroll
    for (int i = 0; i < 4; i++) {
        float4 o;
        o.x = acc[i][0] + pm_b[tx * 4 + 0];
        o.y = acc[i][1] + pm_b[tx * 4 + 1];
        o.z = acc[i][2] + pm_b[tx * 4 + 2];
        o.w = acc[i][3] + pm_b[tx * 4 + 3];
        *(float4*)&g_c1[(size_t)(b * NN + hh * 64 + ty * 4 + i) * 64 + tx * 4] = o;
    }
}

// =====================================================================
// K2: 5 projections fused + channel-attn partial scores.
// As stride 65 (2-way conflicts instead of 8-way at stride 68).
// grid (ptile=64, b=4), block 256, dynamic smem
// =====================================================================
extern __shared__ float smQ[];
__global__ void k_qkv5(const float* __restrict__ w2, const float* __restrict__ b2,
                       const float* __restrict__ w3, const float* __restrict__ b3,
                       const float* __restrict__ w4, const float* __restrict__ b4,
                       const float* __restrict__ w5, const float* __restrict__ b5,
                       const float* __restrict__ w6, const float* __restrict__ b6) {
    float (*As)[65]  = (float(*)[65])smQ;                          // [64][65]
    float (*Ws)[65]  = (float(*)[65])(smQ + 64 * 65);              // [64][65]
    float (*Q2s)[65] = (float(*)[65])(smQ + 64 * 65 + 64 * 65);    // [64][65]
    int b  = blockIdx.y;
    int p0 = blockIdx.x * 64;
    int tid = threadIdx.x;
    int tx = tid & 15, ty = tid >> 4;
    int cg = tid & 15, r0 = tid >> 4;

    for (int rr = r0; rr < 64; rr += 16) {
        float4 av = *(const float4*)&g_c1[(size_t)(b * NN + p0 + rr) * 64 + cg * 4];
        As[rr][cg * 4 + 0] = av.x; As[rr][cg * 4 + 1] = av.y;
        As[rr][cg * 4 + 2] = av.z; As[rr][cg * 4 + 3] = av.w;
    }

    const float* wps[5] = {w2, w3, w4, w5, w6};
    const float* bps[5] = {b2, b3, b4, b5, b6};

    for (int wi = 0; wi < 5; wi++) {
        __syncthreads();
        const float* wp = wps[wi];
        for (int rr = r0; rr < 64; rr += 16) {
            float4 wv = *(const float4*)&wp[rr * 64 + cg * 4];
            Ws[rr][cg * 4 + 0] = wv.x; Ws[rr][cg * 4 + 1] = wv.y;
            Ws[rr][cg * 4 + 2] = wv.z; Ws[rr][cg * 4 + 3] = wv.w;
        }
        __syncthreads();
        float acc[4][4] = {};
        #pragma unroll 8
        for (int c = 0; c < 64; c++) {
            float a[4], wv[4];
            #pragma unroll
            for (int i = 0; i < 4; i++) a[i]  = As[ty * 4 + i][c];
            #pragma unroll
            for (int j = 0; j < 4; j++) wv[j] = Ws[tx * 4 + j][c];
            #pragma unroll
            for (int i = 0; i < 4; i++)
                #pragma unroll
                for (int j = 0; j < 4; j++)
                    acc[i][j] += a[i] * wv[j];
        }
        const float* bp = bps[wi];

        if (wi == 0) {               // q*log2e: bf16x2 words, natural order
            #pragma unroll
            for (int i = 0; i < 4; i++) {
                size_t base = (size_t)(b * NN + p0 + ty * 4 + i) * 32;
                unsigned wlo = pk2((acc[i][0] + bp[tx * 4 + 0]) * LOG2E,
                                   (acc[i][1] + bp[tx * 4 + 1]) * LOG2E);
                unsigned whi = pk2((acc[i][2] + bp[tx * 4 + 2]) * LOG2E,
                                   (acc[i][3] + bp[tx * 4 + 3]) * LOG2E);
                *(uint2*)&g_qw[base + tx * 2] = make_uint2(wlo, whi);
            }
        } else if (wi == 1) {        // k: bf16x2 words, pair-permuted
            #pragma unroll
            for (int i = 0; i < 4; i++) {
                size_t base = (size_t)(b * NN + p0 + ty * 4 + i) * 32;
                unsigned wlo = pk2(acc[i][0] + bp[tx * 4 + 0], acc[i][1] + bp[tx * 4 + 1]);
                unsigned whi = pk2(acc[i][2] + bp[tx * 4 + 2], acc[i][3] + bp[tx * 4 + 3]);
                g_kw[base + permw(2 * tx)]     = wlo;
                g_kw[base + permw(2 * tx + 1)] = whi;
            }
        } else if (wi == 2) {        // v -> stage transposed fp32, then bf16 words
            #pragma unroll
            for (int i = 0; i < 4; i++)
                #pragma unroll
                for (int j = 0; j < 4; j++)
                    Q2s[tx * 4 + j][ty * 4 + i] = acc[i][j] + bp[tx * 4 + j];
            __syncthreads();
            for (int idx = tid; idx < 2048; idx += 256) {
                int ch = idx >> 5, w = idx & 31;
                unsigned val = pk2(Q2s[ch][2 * w], Q2s[ch][2 * w + 1]);
                g_vtw[(size_t)(b * 64 + ch) * (NN / 2) + blockIdx.x * 32 + permw(w)] = val;
            }
        } else if (wi == 3) {        // q2 -> smem (pos-major)
            #pragma unroll
            for (int i = 0; i < 4; i++)
                #pragma unroll
                for (int j = 0; j < 4; j++)
                    Q2s[ty * 4 + i][tx * 4 + j] = acc[i][j] + bp[tx * 4 + j];
        } else {                     // k2 -> As (pos-major), then partial scores
            __syncthreads();
            #pragma unroll
            for (int i = 0; i < 4; i++)
                #pragma unroll
                for (int j = 0; j < 4; j++)
                    As[ty * 4 + i][tx * 4 + j] = acc[i][j] + bp[tx * 4 + j];
            __syncthreads();
            float a2[4][4] = {};
            #pragma unroll 4
            for (int pos = 0; pos < 64; pos++) {
                float qv[4], kv[4];
                #pragma unroll
                for (int i = 0; i < 4; i++) qv[i] = Q2s[pos][ty * 4 + i];
                #pragma unroll
                for (int j = 0; j < 4; j++) kv[j] = As[pos][tx * 4 + j];
                #pragma unroll
                for (int i = 0; i < 4; i++)
                    #pragma unroll
                    for (int j = 0; j < 4; j++)
                        a2[i][j] += qv[i] * kv[j];
            }
            float* dst = &g_spart[(size_t)blockIdx.x * Bb * 4096 + b * 4096];
            #pragma unroll
            for (int i = 0; i < 4; i++)
                *(float4*)&dst[(ty * 4 + i) * 64 + tx * 4] =
                    make_float4(a2[i][0], a2[i][1], a2[i][2], a2[i][3]);
        }
    }
}

// =====================================================================
// K3: flash attention, bf16 mma m16n8k16, split-KV x4, exp2 softmax.
// =====================================================================
__device__ __forceinline__ void mma_bf16(float c[4], const unsigned a[4],
                                         unsigned b0, unsigned b1) {
    asm volatile(
        "mma.sync.aligned.m16n8k16.row.col.f32.bf16.bf16.f32 "
        "{%0,%1,%2,%3}, {%4,%5,%6,%7}, {%8,%9}, {%0,%1,%2,%3};"
        : "+f"(c[0]), "+f"(c[1]), "+f"(c[2]), "+f"(c[3])
        : "r"(a[0]), "r"(a[1]), "r"(a[2]), "r"(a[3]), "r"(b0), "r"(b1));
}
__device__ __forceinline__ unsigned su32(const void* p) {
    return (unsigned)__cvta_generic_to_shared(p);
}

#define SKW 40     // K/V smem row stride (u32 words)
#define SPW 36     // P row stride (u32 words)
#define NSPLIT 4
#define ITERS (64 / NSPLIT)

extern __shared__ unsigned smAu[];
__global__ void __launch_bounds__(128) k_attn1_tc() {
    unsigned* Kb = smAu;                     // [2][64*SKW]
    unsigned* Vb = Kb + 2 * 64 * SKW;        // [2][64*SKW]
    unsigned* Pw = Vb + 2 * 64 * SKW;        // 4 warps * [32*SPW]

    int b   = blockIdx.y;
    int sp  = blockIdx.z;
    int m0  = blockIdx.x * 128;
    int tid = threadIdx.x;
    int w   = tid >> 5, lane = tid & 31;
    int g   = lane >> 2, t = lane & 3;

    const unsigned* Qu = g_qw + (size_t)(b * NN + m0) * 32;
    const unsigned* Kg = g_kw + (size_t)b * NN * 32;
    const unsigned* Vg = g_vtw + (size_t)b * 64 * (NN / 2);
    int it0 = sp * ITERS;

    for (int s = 0; s < 2; s++) {
        const unsigned* kp = Kg + (size_t)(it0 + s) * 64 * 32;
        unsigned* kd = Kb + s * 64 * SKW;
        unsigned* vd = Vb + s * 64 * SKW;
        for (int idx = tid; idx < 512; idx += 128) {
            int r = idx >> 3, c = idx & 7;
            asm volatile("cp.async.cg.shared.global [%0], [%1], 16;" ::
                "r"(su32(kd + r * SKW + c * 4)), "l"(kp + r * 32 + c * 4));
            asm volatile("cp.async.cg.shared.global [%0], [%1], 16;" ::
                "r"(su32(vd + r * SKW + c * 4)),
                "l"(Vg + (size_t)r * (NN / 2) + (size_t)(it0 + s) * 32 + c * 4));
        }
        asm volatile("cp.async.commit_group;");
    }

    unsigned qf[2][4][4];
    #pragma unroll
    for (int rb = 0; rb < 2; rb++) {
        int r1 = 32 * w + 16 * rb + g;
        #pragma unroll
        for (int ka = 0; ka < 4; ka++) {
            qf[rb][ka][0] = Qu[r1 * 32 + 8 * ka + t];
            qf[rb][ka][1] = Qu[(r1 + 8) * 32 + 8 * ka + t];
            qf[rb][ka][2] = Qu[r1 * 32 + 8 * ka + t + 4];
            qf[rb][ka][3] = Qu[(r1 + 8) * 32 + 8 * ka + t + 4];
        }
    }

    unsigned* Pme = Pw + w * 32 * SPW;

    float O[2][8][4] = {};
    float mx[2][2], ls[2][2];
    #pragma unroll
    for (int rb = 0; rb < 2; rb++) {
        mx[rb][0] = mx[rb][1] = -1e30f;
        ls[rb][0] = ls[rb][1] = 0.f;
    }

    for (int j = 0; j < ITERS; j++) {
        asm volatile("cp.async.wait_group 1;" ::: "memory");
        __syncthreads();
        const unsigned* Ks = Kb + (j & 1) * 64 * SKW;
        const unsigned* Vs = Vb + (j & 1) * 64 * SKW;

        // ---- S = Q K^T (S in log2 units: q pre-scaled by log2e) ----
        float S[2][8][4] = {};
        #pragma unroll
        for (int ka = 0; ka < 4; ka++) {
            #pragma unroll
            for (int na = 0; na < 8; na++) {
                uint2 kb = *(const uint2*)&Ks[(8 * na + g) * SKW + 8 * ka + 2 * t];
                mma_bf16(S[0][na], qf[0][ka], kb.x, kb.y);
                mma_bf16(S[1][na], qf[1][ka], kb.x, kb.y);
            }
        }

        // ---- online softmax (base-2) ----
        #pragma unroll
        for (int rb = 0; rb < 2; rb++) {
            float tm1 = -1e30f, tm2 = -1e30f;
            #pragma unroll
            for (int na = 0; na < 8; na++) {
                tm1 = fmaxf(tm1, fmaxf(S[rb][na][0], S[rb][na][1]));
                tm2 = fmaxf(tm2, fmaxf(S[rb][na][2], S[rb][na][3]));
            }
            tm1 = fmaxf(tm1, __shfl_xor_sync(0xffffffffu, tm1, 1));
            tm1 = fmaxf(tm1, __shfl_xor_sync(0xffffffffu, tm1, 2));
            tm2 = fmaxf(tm2, __shfl_xor_sync(0xffffffffu, tm2, 1));
            tm2 = fmaxf(tm2, __shfl_xor_sync(0xffffffffu, tm2, 2));

            float mn1 = fmaxf(mx[rb][0], tm1), mn2 = fmaxf(mx[rb][1], tm2);
            float a1 = ex2(mx[rb][0] - mn1), a2 = ex2(mx[rb][1] - mn2);
            mx[rb][0] = mn1; mx[rb][1] = mn2;

            float rs1 = 0.f, rs2 = 0.f;
            int rowA = (16 * rb + g) * SPW, rowB = (16 * rb + 8 + g) * SPW;
            #pragma unroll
            for (int na = 0; na < 8; na++) {
                float p0 = ex2(S[rb][na][0] - mn1);
                float p1 = ex2(S[rb][na][1] - mn1);
                float p2 = ex2(S[rb][na][2] - mn2);
                float p3 = ex2(S[rb][na][3] - mn2);
                rs1 += p0 + p1; rs2 += p2 + p3;
                Pme[rowA + 4 * na + t] = pk2(p0, p1);
                Pme[rowB + 4 * na + t] = pk2(p2, p3);
            }
            rs1 += __shfl_xor_sync(0xffffffffu, rs1, 1);
            rs1 += __shfl_xor_sync(0xffffffffu, rs1, 2);
            rs2 += __shfl_xor_sync(0xffffffffu, rs2, 1);
            rs2 += __shfl_xor_sync(0xffffffffu, rs2, 2);
            ls[rb][0] = ls[rb][0] * a1 + rs1;
            ls[rb][1] = ls[rb][1] * a2 + rs2;
            #pragma unroll
            for (int na = 0; na < 8; na++) {
                O[rb][na][0] *= a1; O[rb][na][1] *= a1;
                O[rb][na][2] *= a2; O[rb][na][3] *= a2;
            }
        }
        __syncwarp();

        // ---- O += P V ----
        #pragma unroll
        for (int ka = 0; ka < 4; ka++) {
            unsigned pa0[4], pa1[4];
            pa0[0] = Pme[g * SPW + 8 * ka + t];
            pa0[1] = Pme[(8 + g) * SPW + 8 * ka + t];
            pa0[2] = Pme[g * SPW + 8 * ka + t + 4];
            pa0[3] = Pme[(8 + g) * SPW + 8 * ka + t + 4];
            pa1[0] = Pme[(16 + g) * SPW + 8 * ka + t];
            pa1[1] = Pme[(24 + g) * SPW + 8 * ka + t];
            pa1[2] = Pme[(16 + g) * SPW + 8 * ka + t + 4];
            pa1[3] = Pme[(24 + g) * SPW + 8 * ka + t + 4];
            #pragma unroll
            for (int na = 0; na < 8; na++) {
                uint2 vb = *(const uint2*)&Vs[(8 * na + g) * SKW + 8 * ka + 2 * t];
                mma_bf16(O[0][na], pa0, vb.x, vb.y);
                mma_bf16(O[1][na], pa1, vb.x, vb.y);
            }
        }
        __syncthreads();

        int nt = j + 2;
        if (nt < ITERS) {
            const unsigned* kp = Kg + (size_t)(it0 + nt) * 64 * 32;
            unsigned* kd = Kb + (nt & 1) * 64 * SKW;
            unsigned* vd = Vb + (nt & 1) * 64 * SKW;
            for (int idx = tid; idx < 512; idx += 128) {
                int r = idx >> 3, c = idx & 7;
                asm volatile("cp.async.cg.shared.global [%0], [%1], 16;" ::
                    "r"(su32(kd + r * SKW + c * 4)), "l"(kp + r * 32 + c * 4));
                asm volatile("cp.async.cg.shared.global [%0], [%1], 16;" ::
                    "r"(su32(vd + r * SKW + c * 4)),
                    "l"(Vg + (size_t)r * (NN / 2) + (size_t)(it0 + nt) * 32 + c * 4));
            }
        }
        asm volatile("cp.async.commit_group;");
    }

    float* Og = g_o1p + (size_t)(sp * Bb + b) * NN * 64;
    #pragma unroll
    for (int rb = 0; rb < 2; rb++) {
        int r1 = m0 + 32 * w + 16 * rb + g, r2 = r1 + 8;
        #pragma unroll
        for (int na = 0; na < 8; na++) {
            *(float2*)&Og[(size_t)r1 * 64 + 8 * na + 2 * t] =
                make_float2(O[rb][na][0], O[rb][na][1]);
            *(float2*)&Og[(size_t)r2 * 64 + 8 * na + 2 * t] =
                make_float2(O[rb][na][2], O[rb][na][3]);
        }
    }
    if (t == 0) {
        size_t base = (size_t)(sp * Bb + b) * NN + m0 + 32 * w;
        *(float2*)&g_ml[(base + g) * 2]      = make_float2(mx[0][0], ls[0][0]);
        *(float2*)&g_ml[(base + 8 + g) * 2]  = make_float2(mx[0][1], ls[0][1]);
        *(float2*)&g_ml[(base + 16 + g) * 2] = make_float2(mx[1][0], ls[1][0]);
        *(float2*)&g_ml[(base + 24 + g) * 2] = make_float2(mx[1][1], ls[1][1]);
    }
}

// =====================================================================
// K4a: parallel reduce of channel-attn partials: g_spart -> g_s2
// grid (16, Bb), block 256
// =====================================================================
__global__ void k_sreduce() {
    int b = blockIdx.y;
    int e = blockIdx.x * 256 + threadIdx.x;
    const float* src = g_spart + (size_t)b * 4096 + e;
    float s0 = 0.f, s1 = 0.f, s2 = 0.f, s3 = 0.f;
    #pragma unroll 4
    for (int t = 0; t < 64; t += 4) {
        s0 += src[(size_t)(t + 0) * Bb * 4096];
        s1 += src[(size_t)(t + 1) * Bb * 4096];
        s2 += src[(size_t)(t + 2) * Bb * 4096];
        s3 += src[(size_t)(t + 3) * Bb * 4096];
    }
    g_s2[b * 4096 + e] = (s0 + s1) + (s2 + s3);
}

// =====================================================================
// K4b: softmax over d + M = w1_right @ softmax.  grid: b=4
// =====================================================================
__global__ void k_chsoftmax_M(const float* __restrict__ w1) {
    __shared__ float s2s[64][65];
    int b = blockIdx.x;
    int tid = threadIdx.x;

    for (int e4 = tid; e4 < 1024; e4 += 256) {
        float4 v = *(const float4*)&g_s2[b * 4096 + e4 * 4];
        int e = e4 * 4, r = e >> 6, c = e & 63;
        s2s[r][c] = v.x; s2s[r][c + 1] = v.y; s2s[r][c + 2] = v.z; s2s[r][c + 3] = v.w;
    }
    __syncthreads();

    int w = tid >> 5, lane = tid & 31;
    for (int r = w; r < 64; r += 8) {
        float v0 = s2s[r][lane];
        float v1 = s2s[r][lane + 32];
        float m = fmaxf(v0, v1);
        #pragma unroll
        for (int off = 16; off; off >>= 1)
            m = fmaxf(m, __shfl_xor_sync(0xffffffffu, m, off));
        float e0 = __expf(v0 - m), e1 = __expf(v1 - m);
        float s = e0 + e1;
        #pragma unroll
        for (int off = 16; off; off >>= 1)
            s += __shfl_xor_sync(0xffffffffu, s, off);
        float inv = 1.f / s;
        s2s[r][lane] = e0 * inv;
        s2s[r][lane + 32] = e1 * inv;
    }
    __syncthreads();

    int tx = tid & 15, ty = tid >> 4;
    float acc[4][4] = {};
    #pragma unroll 4
    for (int c = 0; c < 64; c++) {
        float wv[4], qv[4];
        #pragma unroll
        for (int i = 0; i < 4; i++) wv[i] = w1[(ty * 4 + i) * 128 + 64 + c];
        #pragma unroll
        for (int j = 0; j < 4; j++) qv[j] = s2s[c][tx * 4 + j];
        #pragma unroll
        for (int i = 0; i < 4; i++)
            #pragma unroll
            for (int j = 0; j < 4; j++)
                acc[i][j] += wv[i] * qv[j];
    }
    #pragma unroll
    for (int i = 0; i < 4; i++)
        #pragma unroll
        for (int j = 0; j < 4; j++)
            g_M[b * 4096 + (ty * 4 + i) * 64 + tx * 4 + j] = acc[i][j];
}

// =====================================================================
// K5: y = w1_left @ combine(4 o1 splits) + M @ v + b1
// As stride 65 (2-way conflicts).
// =====================================================================
__global__ void k_proj(const float* __restrict__ w1, const float* __restrict__ b1) {
    __shared__ float As[64][65];
    __shared__ float Ws[64][65];
    __shared__ float cS[NSPLIT][64];
    int b  = blockIdx.y;
    int p0 = blockIdx.x * 64;
    int tid = threadIdx.x;
    int tx = tid & 15, ty = tid >> 4;
    float acc[4][4] = {};

    if (tid < 64) {
        int row = p0 + tid;
        float2 mlv[NSPLIT];
        float m = -1e30f;
        #pragma unroll
        for (int s = 0; s < NSPLIT; s++) {
            mlv[s] = *(const float2*)&g_ml[((size_t)(s * Bb + b) * NN + row) * 2];
            m = fmaxf(m, mlv[s].x);
        }
        float den = 0.f, co[NSPLIT];
        #pragma unroll
        for (int s = 0; s < NSPLIT; s++) {
            co[s] = ex2(mlv[s].x - m);
            den += co[s] * mlv[s].y;
        }
        float inv = 1.f / den;
        #pragma unroll
        for (int s = 0; s < NSPLIT; s++) cS[s][tid] = co[s] * inv;
    }

    for (int ph = 0; ph < 2; ph++) {
        __syncthreads();
        int cg = tid & 15, r0 = tid >> 4;
        if (ph == 0) {
            for (int rr = r0; rr < 64; rr += 16) {
                float s0 = 0.f, s1 = 0.f, s2 = 0.f, s3 = 0.f;
                #pragma unroll
                for (int s = 0; s < NSPLIT; s++) {
                    float4 o = *(const float4*)&g_o1p[((size_t)(s * Bb + b) * NN + p0 + rr) * 64 + cg * 4];
                    float cf = cS[s][rr];
                    s0 += cf * o.x; s1 += cf * o.y; s2 += cf * o.z; s3 += cf * o.w;
                }
                As[rr][cg * 4 + 0] = s0; As[rr][cg * 4 + 1] = s1;
                As[rr][cg * 4 + 2] = s2; As[rr][cg * 4 + 3] = s3;
                float4 wv = *(const float4*)&w1[rr * 128 + cg * 4];
                Ws[rr][cg * 4 + 0] = wv.x; Ws[rr][cg * 4 + 1] = wv.y;
                Ws[rr][cg * 4 + 2] = wv.z; Ws[rr][cg * 4 + 3] = wv.w;
            }
        } else {
            // reconstruct v (fp32) from packed bf16 g_vtw (inverse pair-perm)
            for (int idx = tid; idx < 2048; idx += 256) {
                int ch = idx >> 5, p = idx & 31;
                int i7 = p & 7;
                int wo = (p & ~7) | (i7 >> 1) | ((i7 & 1) << 2);
                unsigned val = g_vtw[(size_t)(b * 64 + ch) * (NN / 2) + blockIdx.x * 32 + p];
                __nv_bfloat162 h = *reinterpret_cast<__nv_bfloat162*>(&val);
                As[2 * wo][ch]     = __bfloat162float(h.x);
                As[2 * wo + 1][ch] = __bfloat162float(h.y);
            }
            for (int rr = r0; rr < 64; rr += 16) {
                float4 wv = *(const float4*)&g_M[b * 4096 + rr * 64 + cg * 4];
                Ws[rr][cg * 4 + 0] = wv.x; Ws[rr][cg * 4 + 1] = wv.y;
                Ws[rr][cg * 4 + 2] = wv.z; Ws[rr][cg * 4 + 3] = wv.w;
            }
        }
        __syncthreads();
        #pragma unroll 8
        for (int c = 0; c < 64; c++) {
            float a[4], wv[4];
            #pragma unroll
            for (int i = 0; i < 4; i++) a[i]  = As[ty * 4 + i][c];
            #pragma unroll
            for (int j = 0; j < 4; j++) wv[j] = Ws[tx * 4 + j][c];
            #pragma unroll
            for (int i = 0; i < 4; i++)
                #pragma unroll
                for (int j = 0; j < 4; j++)
                    acc[i][j] += a[i] * wv[j];
        }
    }
    #pragma unroll
    for (int i = 0; i < 4; i++) {
        float4 o;
        o.x = acc[i][0] + b1[tx * 4 + 0];
        o.y = acc[i][1] + b1[tx * 4 + 1];
        o.z = acc[i][2] + b1[tx * 4 + 2];
        o.w = acc[i][3] + b1[tx * 4 + 3];
        *(float4*)&g_y[(size_t)(b * NN + p0 + ty * 4 + i) * 64 + tx * 4] = o;
    }
}

// =====================================================================
// K6: bilinear 2x upsample + residual, coalesced.
// grid (128, Bb), block 256
// =====================================================================
__global__ void k_upsample2(const float* __restrict__ x, float* __restrict__ out) {
    __shared__ float Y[2][64 * 66];
    int b = blockIdx.y, i = blockIdx.x;
    int tid = threadIdx.x;
    int p = i >> 1;
    int r0, r1; float wy0, wy1;
    if (i & 1) { r0 = p; r1 = (p + 1 < 64) ? p + 1 : 63; wy0 = 0.75f; wy1 = 0.25f; }
    else       { r0 = (p > 0) ? p - 1 : 0; r1 = p;       wy0 = 0.25f; wy1 = 0.75f; }

    const float* yb = g_y + (size_t)b * NN * 64;
    int rows[2] = {r0, r1};
    for (int e2 = tid; e2 < 4096; e2 += 256) {
        int rr  = e2 >> 11;
        int rem = e2 & 2047;
        int s   = rem >> 5;
        int c2  = rem & 31;
        float2 v = *(const float2*)&yb[((rows[rr] * 64 + s) * 64) + c2 * 2];
        *(float2*)&Y[rr][s * 66 + c2 * 2] = v;
    }
    __syncthreads();

    size_t obase = ((size_t)b * 64 * 128 + i) * 128;
    for (int e = tid; e < 8192; e += 256) {
        int c = e >> 7, j = e & 127;
        int q = j >> 1;
        int s0, s1; float wx0, wx1;
        if (j & 1) { s0 = q; s1 = (q + 1 < 64) ? q + 1 : 63; wx0 = 0.75f; wx1 = 0.25f; }
        else       { s0 = (q > 0) ? q - 1 : 0; s1 = q;       wx0 = 0.25f; wx1 = 0.75f; }
        float v = wy0 * (wx0 * Y[0][s0 * 66 + c] + wx1 * Y[0][s1 * 66 + c])
                + wy1 * (wx0 * Y[1][s0 * 66 + c] + wx1 * Y[1][s1 * 66 + c]);
        size_t oi = obase + (size_t)c * 16384 + j;
        out[oi] = v + x[oi];
    }
}

// =====================================================================
extern "C" void kernel_launch(void* const* d_in, const int* in_sizes, int n_in,
                              void* d_out, int out_size) {
    const float* x        = (const float*)d_in[0];
    const float* pm_gamma = (const float*)d_in[1];
    const float* pm_beta  = (const float*)d_in[2];
    const float* pm_w     = (const float*)d_in[3];
    const float* pm_b     = (const float*)d_in[4];
    const float* w2 = (const float*)d_in[5];
    const float* b2 = (const float*)d_in[6];
    const float* w3 = (const float*)d_in[7];
    const float* b3 = (const float*)d_in[8];
    const float* w4 = (const float*)d_in[9];
    const float* b4 = (const float*)d_in[10];
    const float* w5 = (const float*)d_in[11];
    const float* b5 = (const float*)d_in[12];
    const float* w6 = (const float*)d_in[13];
    const float* b6 = (const float*)d_in[14];
    const float* w1 = (const float*)d_in[15];
    const float* b1 = (const float*)d_in[16];
    float* out = (float*)d_out;

    const int merge_smem = (256 * 65 + 64 * 65) * 4;                  // 83200 B
    const int qkv_smem   = (64 * 65 * 3) * 4;                         // 49920 B
    const int attn_smem  = (2 * 64 * SKW * 2 + 4 * 32 * SPW) * 4;     // 59392 B
    cudaFuncSetAttribute(k_merge_pml, cudaFuncAttributeMaxDynamicSharedMemorySize, merge_smem);
    cudaFuncSetAttribute(k_qkv5,      cudaFuncAttributeMaxDynamicSharedMemorySize, qkv_smem);
    cudaFuncSetAttribute(k_attn1_tc,  cudaFuncAttributeMaxDynamicSharedMemorySize, attn_smem);

    k_merge_pml  <<<dim3(64, Bb), 256, merge_smem>>>(x, pm_gamma, pm_beta, pm_w, pm_b);
    k_qkv5       <<<dim3(64, Bb), 256, qkv_smem>>>(w2, b2, w3, b3, w4, b4, w5, b5, w6, b6);
    k_sreduce    <<<dim3(16, Bb), 256>>>();
    k_attn1_tc   <<<dim3(32, Bb, NSPLIT), 128, attn_smem>>>();
    k_chsoftmax_M<<<Bb, 256>>>(w1);
    k_proj       <<<dim3(64, Bb), 256>>>(w1, b1);
    k_upsample2  <<<dim3(128, Bb), 256>>>(x, out);
}

// round 14
// speedup vs baseline: 1.0261x; 1.0261x over previous
#include <cuda_runtime.h>
#include <cuda_bf16.h>

#define Bb 4
#define Cc 64
#define NN 4096    // 64*64 merged positions
#define HH 128
#define WW 128
#define LOG2E 1.4426950408889634f

// -------- scratch (static device globals) --------
__device__ float    g_c1[Bb*NN*Cc];        // (B,N,64)
__device__ unsigned g_qw [Bb*NN*32];       // q*log2e bf16x2 words (natural ch order)
__device__ unsigned g_kw [Bb*NN*32];       // k bf16x2 words (natural ch order)
__device__ unsigned g_vtw[Bb*64*(NN/2)];   // v bf16x2 [b][ch][pos-pair] natural order
__device__ float    g_o1p[2*Bb*NN*Cc];     // split-KV unnormalized partial O
__device__ float    g_ml [2*Bb*NN*2];      // split-KV per-row (m, l), m in log2 units
__device__ float    g_y  [Bb*NN*Cc];       // pre-upsample output
__device__ float    g_spart[64*Bb*64*64];  // channel-attn partial scores per pos-tile
__device__ float    g_s2 [Bb*64*64];       // reduced channel-attn scores
__device__ float    g_M  [Bb*64*64];       // w1_right @ softmax(scores)

__device__ __forceinline__ unsigned pk2(float lo, float hi) {
    __nv_bfloat162 h = __floats2bfloat162_rn(lo, hi);
    return *reinterpret_cast<unsigned*>(&h);
}
__device__ __forceinline__ float ex2(float x) {
    float r;
    asm("ex2.approx.f32 %0, %1;" : "=f"(r) : "f"(x));
    return r;
}

// =====================================================================
// K1: fused patch-merge + LayerNorm + pm linear (256->64)
// grid (hh=64, b=4), block 256
// =====================================================================
extern __shared__ float smM[];
__global__ void k_merge_pml(const float* __restrict__ x,
                            const float* __restrict__ gamma,
                            const float* __restrict__ beta,
                            const float* __restrict__ pm_w,
                            const float* __restrict__ pm_b) {
    float (*ts)[65] = (float(*)[65])smM;              // [256][65]
    float (*Ws)[65] = (float(*)[65])(smM + 256 * 65); // [64][65]
    __shared__ float s_mu[64], s_rs[64];
    int b = blockIdx.y, hh = blockIdx.x, tid = threadIdx.x;

    for (int e = tid; e < 8192; e += 256) {
        int c2 = e >> 6;
        int p  = e & 63;
        int dr = c2 >> 6;
        int ch = c2 & 63;
        float2 v = *(const float2*)&x[(((b * 64 + ch) * 128) + 2 * hh + dr) * 128 + 2 * p];
        ts[dr * 64 + ch][p]       = v.x;
        ts[dr * 64 + ch + 128][p] = v.y;
    }
    __syncthreads();

    int w = tid >> 5, lane = tid & 31;
    for (int p = w * 8; p < w * 8 + 8; p++) {
        float s = 0.f, ss = 0.f;
        for (int c = lane; c < 256; c += 32) {
            float v = ts[c][p];
            s += v; ss += v * v;
        }
        #pragma unroll
        for (int off = 16; off; off >>= 1) {
            s  += __shfl_xor_sync(0xffffffffu, s,  off);
            ss += __shfl_xor_sync(0xffffffffu, ss, off);
        }
        float mu  = s * (1.f / 256.f);
        float var = ss * (1.f / 256.f) - mu * mu;
        if (lane == 0) { s_mu[p] = mu; s_rs[p] = rsqrtf(var + 1e-5f); }
    }
    __syncthreads();

    for (int e = tid; e < 16384; e += 256) {
        int c = e >> 6, p = e & 63;
        ts[c][p] = (ts[c][p] - s_mu[p]) * s_rs[p] * gamma[c] + beta[c];
    }

    int tx = tid & 15, ty = tid >> 4;
    float acc[4][4] = {};
    for (int kc = 0; kc < 4; kc++) {
        __syncthreads();
        int cg = tid & 15, r0 = tid >> 4;
        for (int rr = r0; rr < 64; rr += 16) {
            float4 wv = *(const float4*)&pm_w[rr * 256 + kc * 64 + cg * 4];
            Ws[rr][cg * 4 + 0] = wv.x; Ws[rr][cg * 4 + 1] = wv.y;
            Ws[rr][cg * 4 + 2] = wv.z; Ws[rr][cg * 4 + 3] = wv.w;
        }
        __syncthreads();
        #pragma unroll 8
        for (int c = 0; c < 64; c++) {
            float a[4], wv[4];
            #pragma unroll
            for (int i = 0; i < 4; i++) a[i]  = ts[kc * 64 + c][ty * 4 + i];
            #pragma unroll
            for (int j = 0; j < 4; j++) wv[j] = Ws[tx * 4 + j][c];
            #pragma unroll
            for (int i = 0; i < 4; i++)
                #pragma unroll
                for (int j = 0; j < 4; j++)
                    acc[i][j] += a[i] * wv[j];
        }
    }
    #pragma unroll
    for (int i = 0; i < 4; i++) {
        float4 o;
        o.x = acc[i][0] + pm_b[tx * 4 + 0];
        o.y = acc[i][1] + pm_b[tx * 4 + 1];
        o.z = acc[i][2] + pm_b[tx * 4 + 2];
        o.w = acc[i][3] + pm_b[tx * 4 + 3];
        *(float4*)&g_c1[(size_t)(b * NN + hh * 64 + ty * 4 + i) * 64 + tx * 4] = o;
    }
}

// =====================================================================
// K2: 5 projections fused + channel-attn partial scores.
// As stride 68 + float4 stores (R12 layout; broadcast makes A-loads clean).
// grid (ptile=64, b=4), block 256, dynamic smem
// =====================================================================
extern __shared__ float smQ[];
__global__ void k_qkv5(const float* __restrict__ w2, const float* __restrict__ b2,
                       const float* __restrict__ w3, const float* __restrict__ b3,
                       const float* __restrict__ w4, const float* __restrict__ b4,
                       const float* __restrict__ w5, const float* __restrict__ b5,
                       const float* __restrict__ w6, const float* __restrict__ b6) {
    float (*As)[68]  = (float(*)[68])smQ;                          // [64][68]
    float (*Ws)[65]  = (float(*)[65])(smQ + 64 * 68);              // [64][65]
    float (*Q2s)[65] = (float(*)[65])(smQ + 64 * 68 + 64 * 65);    // [64][65]
    int b  = blockIdx.y;
    int p0 = blockIdx.x * 64;
    int tid = threadIdx.x;
    int tx = tid & 15, ty = tid >> 4;
    int cg = tid & 15, r0 = tid >> 4;

    for (int rr = r0; rr < 64; rr += 16)
        *(float4*)&As[rr][cg * 4] =
            *(const float4*)&g_c1[(size_t)(b * NN + p0 + rr) * 64 + cg * 4];

    const float* wps[5] = {w2, w3, w4, w5, w6};
    const float* bps[5] = {b2, b3, b4, b5, b6};

    for (int wi = 0; wi < 5; wi++) {
        __syncthreads();
        const float* wp = wps[wi];
        for (int rr = r0; rr < 64; rr += 16) {
            float4 wv = *(const float4*)&wp[rr * 64 + cg * 4];
            Ws[rr][cg * 4 + 0] = wv.x; Ws[rr][cg * 4 + 1] = wv.y;
            Ws[rr][cg * 4 + 2] = wv.z; Ws[rr][cg * 4 + 3] = wv.w;
        }
        __syncthreads();
        float acc[4][4] = {};
        #pragma unroll 8
        for (int c = 0; c < 64; c++) {
            float a[4], wv[4];
            #pragma unroll
            for (int i = 0; i < 4; i++) a[i]  = As[ty * 4 + i][c];
            #pragma unroll
            for (int j = 0; j < 4; j++) wv[j] = Ws[tx * 4 + j][c];
            #pragma unroll
            for (int i = 0; i < 4; i++)
                #pragma unroll
                for (int j = 0; j < 4; j++)
                    acc[i][j] += a[i] * wv[j];
        }
        const float* bp = bps[wi];

        if (wi == 0) {               // q*log2e: bf16x2 words, natural order
            #pragma unroll
            for (int i = 0; i < 4; i++) {
                size_t base = (size_t)(b * NN + p0 + ty * 4 + i) * 32;
                unsigned wlo = pk2((acc[i][0] + bp[tx * 4 + 0]) * LOG2E,
                                   (acc[i][1] + bp[tx * 4 + 1]) * LOG2E);
                unsigned whi = pk2((acc[i][2] + bp[tx * 4 + 2]) * LOG2E,
                                   (acc[i][3] + bp[tx * 4 + 3]) * LOG2E);
                *(uint2*)&g_qw[base + tx * 2] = make_uint2(wlo, whi);
            }
        } else if (wi == 1) {        // k: bf16x2 words, natural order
            #pragma unroll
            for (int i = 0; i < 4; i++) {
                size_t base = (size_t)(b * NN + p0 + ty * 4 + i) * 32;
                unsigned wlo = pk2(acc[i][0] + bp[tx * 4 + 0], acc[i][1] + bp[tx * 4 + 1]);
                unsigned whi = pk2(acc[i][2] + bp[tx * 4 + 2], acc[i][3] + bp[tx * 4 + 3]);
                *(uint2*)&g_kw[base + tx * 2] = make_uint2(wlo, whi);
            }
        } else if (wi == 2) {        // v -> stage transposed fp32, then bf16 words
            #pragma unroll
            for (int i = 0; i < 4; i++)
                #pragma unroll
                for (int j = 0; j < 4; j++)
                    Q2s[tx * 4 + j][ty * 4 + i] = acc[i][j] + bp[tx * 4 + j];
            __syncthreads();
            for (int idx = tid; idx < 2048; idx += 256) {
                int ch = idx >> 5, w = idx & 31;
                unsigned val = pk2(Q2s[ch][2 * w], Q2s[ch][2 * w + 1]);
                g_vtw[(size_t)(b * 64 + ch) * (NN / 2) + blockIdx.x * 32 + w] = val;
            }
        } else if (wi == 3) {        // q2 -> smem (pos-major)
            #pragma unroll
            for (int i = 0; i < 4; i++)
                #pragma unroll
                for (int j = 0; j < 4; j++)
                    Q2s[ty * 4 + i][tx * 4 + j] = acc[i][j] + bp[tx * 4 + j];
        } else {                     // k2 -> As (pos-major), then partial scores
            __syncthreads();
            #pragma unroll
            for (int i = 0; i < 4; i++)
                #pragma unroll
                for (int j = 0; j < 4; j++)
                    As[ty * 4 + i][tx * 4 + j] = acc[i][j] + bp[tx * 4 + j];
            __syncthreads();
            float a2[4][4] = {};
            #pragma unroll 4
            for (int pos = 0; pos < 64; pos++) {
                float qv[4], kv[4];
                #pragma unroll
                for (int i = 0; i < 4; i++) qv[i] = Q2s[pos][ty * 4 + i];
                #pragma unroll
                for (int j = 0; j < 4; j++) kv[j] = As[pos][tx * 4 + j];
                #pragma unroll
                for (int i = 0; i < 4; i++)
                    #pragma unroll
                    for (int j = 0; j < 4; j++)
                        a2[i][j] += qv[i] * kv[j];
            }
            float* dst = &g_spart[(size_t)blockIdx.x * Bb * 4096 + b * 4096];
            #pragma unroll
            for (int i = 0; i < 4; i++)
                *(float4*)&dst[(ty * 4 + i) * 64 + tx * 4] =
                    make_float4(a2[i][0], a2[i][1], a2[i][2], a2[i][3]);
        }
    }
}

// =====================================================================
// K3: flash attention, bf16 mma m16n8k16, split-KV x2, exp2 softmax,
// ldmatrix.x4 fragment loads. K smem [n][k], V smem [ch][pos], P [m][k];
// all row stride 36 words -> every ldmatrix phase conflict-free.
// =====================================================================
__device__ __forceinline__ void mma_bf16(float c[4], const unsigned a[4],
                                         unsigned b0, unsigned b1) {
    asm volatile(
        "mma.sync.aligned.m16n8k16.row.col.f32.bf16.bf16.f32 "
        "{%0,%1,%2,%3}, {%4,%5,%6,%7}, {%8,%9}, {%0,%1,%2,%3};"
        : "+f"(c[0]), "+f"(c[1]), "+f"(c[2]), "+f"(c[3])
        : "r"(a[0]), "r"(a[1]), "r"(a[2]), "r"(a[3]), "r"(b0), "r"(b1));
}
__device__ __forceinline__ void ldsm_x4(unsigned& r0, unsigned& r1,
                                        unsigned& r2, unsigned& r3, unsigned addr) {
    asm volatile("ldmatrix.sync.aligned.m8n8.x4.shared.b16 {%0,%1,%2,%3}, [%4];"
        : "=r"(r0), "=r"(r1), "=r"(r2), "=r"(r3) : "r"(addr));
}
__device__ __forceinline__ unsigned su32(const void* p) {
    return (unsigned)__cvta_generic_to_shared(p);
}

#define SKW 36     // K/V smem row stride (u32 words)
#define SPW 36     // P row stride (u32 words)
#define NSPLIT 2
#define ITERS (64 / NSPLIT)

extern __shared__ unsigned smAu[];
__global__ void __launch_bounds__(128) k_attn1_tc() {
    unsigned* Kb = smAu;                     // [2][64*SKW]
    unsigned* Vb = Kb + 2 * 64 * SKW;        // [2][64*SKW]
    unsigned* Pw = Vb + 2 * 64 * SKW;        // 4 warps * [32*SPW]

    int b   = blockIdx.y;
    int sp  = blockIdx.z;
    int m0  = blockIdx.x * 128;
    int tid = threadIdx.x;
    int w   = tid >> 5, lane = tid & 31;
    int g   = lane >> 2, t = lane & 3;
    int mm  = lane >> 3, rr8 = lane & 7;
    int bn_add = ((mm >> 1) << 3) + rr8;     // K/V: row-in-16 block
    int bk_add = (mm & 1) << 2;              // K/V: k-half word offset
    int pm_add = ((mm & 1) << 3) + rr8;      // P: row-in-16 block
    int pk_add = (mm >> 1) << 2;             // P: k-half word offset

    const unsigned* Qu = g_qw + (size_t)(b * NN + m0) * 32;
    const unsigned* Kg = g_kw + (size_t)b * NN * 32;
    const unsigned* Vg = g_vtw + (size_t)b * 64 * (NN / 2);
    int it0 = sp * ITERS;

    for (int s = 0; s < 2; s++) {
        const unsigned* kp = Kg + (size_t)(it0 + s) * 64 * 32;
        unsigned* kd = Kb + s * 64 * SKW;
        unsigned* vd = Vb + s * 64 * SKW;
        for (int idx = tid; idx < 512; idx += 128) {
            int r = idx >> 3, c = idx & 7;
            asm volatile("cp.async.cg.shared.global [%0], [%1], 16;" ::
                "r"(su32(kd + r * SKW + c * 4)), "l"(kp + r * 32 + c * 4));
            asm volatile("cp.async.cg.shared.global [%0], [%1], 16;" ::
                "r"(su32(vd + r * SKW + c * 4)),
                "l"(Vg + (size_t)r * (NN / 2) + (size_t)(it0 + s) * 32 + c * 4));
        }
        asm volatile("cp.async.commit_group;");
    }

    unsigned qf[2][4][4];
    #pragma unroll
    for (int rb = 0; rb < 2; rb++) {
        int r1 = 32 * w + 16 * rb + g;
        #pragma unroll
        for (int ka = 0; ka < 4; ka++) {
            qf[rb][ka][0] = Qu[r1 * 32 + 8 * ka + t];
            qf[rb][ka][1] = Qu[(r1 + 8) * 32 + 8 * ka + t];
            qf[rb][ka][2] = Qu[r1 * 32 + 8 * ka + t + 4];
            qf[rb][ka][3] = Qu[(r1 + 8) * 32 + 8 * ka + t + 4];
        }
    }

    unsigned* Pme = Pw + w * 32 * SPW;
    unsigned pme_base = su32(Pme);

    float O[2][8][4] = {};
    float mx[2][2], ls[2][2];
    #pragma unroll
    for (int rb = 0; rb < 2; rb++) {
        mx[rb][0] = mx[rb][1] = -1e30f;
        ls[rb][0] = ls[rb][1] = 0.f;
    }

    for (int j = 0; j < ITERS; j++) {
        asm volatile("cp.async.wait_group 1;" ::: "memory");
        __syncthreads();
        unsigned ks_base = su32(Kb + (j & 1) * 64 * SKW);
        unsigned vs_base = su32(Vb + (j & 1) * 64 * SKW);

        // ---- S = Q K^T (log2 units) ----
        float S[2][8][4] = {};
        #pragma unroll
        for (int ka = 0; ka < 4; ka++) {
            #pragma unroll
            for (int np = 0; np < 4; np++) {
                unsigned b00, b01, b10, b11;
                ldsm_x4(b00, b01, b10, b11,
                        ks_base + (((16 * np + bn_add) * SKW + 8 * ka + bk_add) << 2));
                mma_bf16(S[0][2 * np],     qf[0][ka], b00, b01);
                mma_bf16(S[1][2 * np],     qf[1][ka], b00, b01);
                mma_bf16(S[0][2 * np + 1], qf[0][ka], b10, b11);
                mma_bf16(S[1][2 * np + 1], qf[1][ka], b10, b11);
            }
        }

        // ---- online softmax (base-2) ----
        #pragma unroll
        for (int rb = 0; rb < 2; rb++) {
            float tm1 = -1e30f, tm2 = -1e30f;
            #pragma unroll
            for (int na = 0; na < 8; na++) {
                tm1 = fmaxf(tm1, fmaxf(S[rb][na][0], S[rb][na][1]));
                tm2 = fmaxf(tm2, fmaxf(S[rb][na][2], S[rb][na][3]));
            }
            tm1 = fmaxf(tm1, __shfl_xor_sync(0xffffffffu, tm1, 1));
            tm1 = fmaxf(tm1, __shfl_xor_sync(0xffffffffu, tm1, 2));
            tm2 = fmaxf(tm2, __shfl_xor_sync(0xffffffffu, tm2, 1));
            tm2 = fmaxf(tm2, __shfl_xor_sync(0xffffffffu, tm2, 2));

            float mn1 = fmaxf(mx[rb][0], tm1), mn2 = fmaxf(mx[rb][1], tm2);
            float a1 = ex2(mx[rb][0] - mn1), a2 = ex2(mx[rb][1] - mn2);
            mx[rb][0] = mn1; mx[rb][1] = mn2;

            float rs1 = 0.f, rs2 = 0.f;
            int rowA = (16 * rb + g) * SPW, rowB = (16 * rb + 8 + g) * SPW;
            #pragma unroll
            for (int na = 0; na < 8; na++) {
                float p0 = ex2(S[rb][na][0] - mn1);
                float p1 = ex2(S[rb][na][1] - mn1);
                float p2 = ex2(S[rb][na][2] - mn2);
                float p3 = ex2(S[rb][na][3] - mn2);
                rs1 += p0 + p1; rs2 += p2 + p3;
                Pme[rowA + 4 * na + t] = pk2(p0, p1);
                Pme[rowB + 4 * na + t] = pk2(p2, p3);
            }
            rs1 += __shfl_xor_sync(0xffffffffu, rs1, 1);
            rs1 += __shfl_xor_sync(0xffffffffu, rs1, 2);
            rs2 += __shfl_xor_sync(0xffffffffu, rs2, 1);
            rs2 += __shfl_xor_sync(0xffffffffu, rs2, 2);
            ls[rb][0] = ls[rb][0] * a1 + rs1;
            ls[rb][1] = ls[rb][1] * a2 + rs2;
            #pragma unroll
            for (int na = 0; na < 8; na++) {
                O[rb][na][0] *= a1; O[rb][na][1] *= a1;
                O[rb][na][2] *= a2; O[rb][na][3] *= a2;
            }
        }
        __syncwarp();

        // ---- O += P V ----
        #pragma unroll
        for (int ka = 0; ka < 4; ka++) {
            unsigned pa0[4], pa1[4];
            ldsm_x4(pa0[0], pa0[1], pa0[2], pa0[3],
                    pme_base + ((pm_add * SPW + 8 * ka + pk_add) << 2));
            ldsm_x4(pa1[0], pa1[1], pa1[2], pa1[3],
                    pme_base + (((16 + pm_add) * SPW + 8 * ka + pk_add) << 2));
            #pragma unroll
            for (int np = 0; np < 4; np++) {
                unsigned v00, v01, v10, v11;
                ldsm_x4(v00, v01, v10, v11,
                        vs_base + (((16 * np + bn_add) * SKW + 8 * ka + bk_add) << 2));
                mma_bf16(O[0][2 * np],     pa0, v00, v01);
                mma_bf16(O[1][2 * np],     pa1, v00, v01);
                mma_bf16(O[0][2 * np + 1], pa0, v10, v11);
                mma_bf16(O[1][2 * np + 1], pa1, v10, v11);
            }
        }
        __syncthreads();

        int nt = j + 2;
        if (nt < ITERS) {
            const unsigned* kp = Kg + (size_t)(it0 + nt) * 64 * 32;
            unsigned* kd = Kb + (nt & 1) * 64 * SKW;
            unsigned* vd = Vb + (nt & 1) * 64 * SKW;
            for (int idx = tid; idx < 512; idx += 128) {
                int r = idx >> 3, c = idx & 7;
                asm volatile("cp.async.cg.shared.global [%0], [%1], 16;" ::
                    "r"(su32(kd + r * SKW + c * 4)), "l"(kp + r * 32 + c * 4));
                asm volatile("cp.async.cg.shared.global [%0], [%1], 16;" ::
                    "r"(su32(vd + r * SKW + c * 4)),
                    "l"(Vg + (size_t)r * (NN / 2) + (size_t)(it0 + nt) * 32 + c * 4));
            }
        }
        asm volatile("cp.async.commit_group;");
    }

    float* Og = g_o1p + (size_t)(sp * Bb + b) * NN * 64;
    #pragma unroll
    for (int rb = 0; rb < 2; rb++) {
        int r1 = m0 + 32 * w + 16 * rb + g, r2 = r1 + 8;
        #pragma unroll
        for (int na = 0; na < 8; na++) {
            *(float2*)&Og[(size_t)r1 * 64 + 8 * na + 2 * t] =
                make_float2(O[rb][na][0], O[rb][na][1]);
            *(float2*)&Og[(size_t)r2 * 64 + 8 * na + 2 * t] =
                make_float2(O[rb][na][2], O[rb][na][3]);
        }
    }
    if (t == 0) {
        size_t base = (size_t)(sp * Bb + b) * NN + m0 + 32 * w;
        *(float2*)&g_ml[(base + g) * 2]      = make_float2(mx[0][0], ls[0][0]);
        *(float2*)&g_ml[(base + 8 + g) * 2]  = make_float2(mx[0][1], ls[0][1]);
        *(float2*)&g_ml[(base + 16 + g) * 2] = make_float2(mx[1][0], ls[1][0]);
        *(float2*)&g_ml[(base + 24 + g) * 2] = make_float2(mx[1][1], ls[1][1]);
    }
}

// =====================================================================
// K4a: parallel reduce of channel-attn partials: g_spart -> g_s2
// grid (16, Bb), block 256
// =====================================================================
__global__ void k_sreduce() {
    int b = blockIdx.y;
    int e = blockIdx.x * 256 + threadIdx.x;
    const float* src = g_spart + (size_t)b * 4096 + e;
    float s0 = 0.f, s1 = 0.f, s2 = 0.f, s3 = 0.f;
    #pragma unroll 4
    for (int t = 0; t < 64; t += 4) {
        s0 += src[(size_t)(t + 0) * Bb * 4096];
        s1 += src[(size_t)(t + 1) * Bb * 4096];
        s2 += src[(size_t)(t + 2) * Bb * 4096];
        s3 += src[(size_t)(t + 3) * Bb * 4096];
    }
    g_s2[b * 4096 + e] = (s0 + s1) + (s2 + s3);
}

// =====================================================================
// K4b: softmax over d + M = w1_right @ softmax.  grid: b=4
// =====================================================================
__global__ void k_chsoftmax_M(const float* __restrict__ w1) {
    __shared__ float s2s[64][65];
    int b = blockIdx.x;
    int tid = threadIdx.x;

    for (int e4 = tid; e4 < 1024; e4 += 256) {
        float4 v = *(const float4*)&g_s2[b * 4096 + e4 * 4];
        int e = e4 * 4, r = e >> 6, c = e & 63;
        s2s[r][c] = v.x; s2s[r][c + 1] = v.y; s2s[r][c + 2] = v.z; s2s[r][c + 3] = v.w;
    }
    __syncthreads();

    int w = tid >> 5, lane = tid & 31;
    for (int r = w; r < 64; r += 8) {
        float v0 = s2s[r][lane];
        float v1 = s2s[r][lane + 32];
        float m = fmaxf(v0, v1);
        #pragma unroll
        for (int off = 16; off; off >>= 1)
            m = fmaxf(m, __shfl_xor_sync(0xffffffffu, m, off));
        float e0 = __expf(v0 - m), e1 = __expf(v1 - m);
        float s = e0 + e1;
        #pragma unroll
        for (int off = 16; off; off >>= 1)
            s += __shfl_xor_sync(0xffffffffu, s, off);
        float inv = 1.f / s;
        s2s[r][lane] = e0 * inv;
        s2s[r][lane + 32] = e1 * inv;
    }
    __syncthreads();

    int tx = tid & 15, ty = tid >> 4;
    float acc[4][4] = {};
    #pragma unroll 4
    for (int c = 0; c < 64; c++) {
        float wv[4], qv[4];
        #pragma unroll
        for (int i = 0; i < 4; i++) wv[i] = w1[(ty * 4 + i) * 128 + 64 + c];
        #pragma unroll
        for (int j = 0; j < 4; j++) qv[j] = s2s[c][tx * 4 + j];
        #pragma unroll
        for (int i = 0; i < 4; i++)
            #pragma unroll
            for (int j = 0; j < 4; j++)
                acc[i][j] += wv[i] * qv[j];
    }
    #pragma unroll
    for (int i = 0; i < 4; i++)
        #pragma unroll
        for (int j = 0; j < 4; j++)
            g_M[b * 4096 + (ty * 4 + i) * 64 + tx * 4 + j] = acc[i][j];
}

// =====================================================================
// K5: y = w1_left @ combine(o1 splits) + M @ v + b1
// =====================================================================
__global__ void k_proj(const float* __restrict__ w1, const float* __restrict__ b1) {
    __shared__ float As[64][68];
    __shared__ float Ws[64][65];
    __shared__ float cS[NSPLIT][64];
    int b  = blockIdx.y;
    int p0 = blockIdx.x * 64;
    int tid = threadIdx.x;
    int tx = tid & 15, ty = tid >> 4;
    float acc[4][4] = {};

    if (tid < 64) {
        int row = p0 + tid;
        float2 mlv[NSPLIT];
        float m = -1e30f;
        #pragma unroll
        for (int s = 0; s < NSPLIT; s++) {
            mlv[s] = *(const float2*)&g_ml[((size_t)(s * Bb + b) * NN + row) * 2];
            m = fmaxf(m, mlv[s].x);
        }
        float den = 0.f, co[NSPLIT];
        #pragma unroll
        for (int s = 0; s < NSPLIT; s++) {
            co[s] = ex2(mlv[s].x - m);
            den += co[s] * mlv[s].y;
        }
        float inv = 1.f / den;
        #pragma unroll
        for (int s = 0; s < NSPLIT; s++) cS[s][tid] = co[s] * inv;
    }

    for (int ph = 0; ph < 2; ph++) {
        __syncthreads();
        int cg = tid & 15, r0 = tid >> 4;
        if (ph == 0) {
            for (int rr = r0; rr < 64; rr += 16) {
                float s0 = 0.f, s1 = 0.f, s2 = 0.f, s3 = 0.f;
                #pragma unroll
                for (int s = 0; s < NSPLIT; s++) {
                    float4 o = *(const float4*)&g_o1p[((size_t)(s * Bb + b) * NN + p0 + rr) * 64 + cg * 4];
                    float cf = cS[s][rr];
                    s0 += cf * o.x; s1 += cf * o.y; s2 += cf * o.z; s3 += cf * o.w;
                }
                *(float4*)&As[rr][cg * 4] = make_float4(s0, s1, s2, s3);
                float4 wv = *(const float4*)&w1[rr * 128 + cg * 4];
                Ws[rr][cg * 4 + 0] = wv.x; Ws[rr][cg * 4 + 1] = wv.y;
                Ws[rr][cg * 4 + 2] = wv.z; Ws[rr][cg * 4 + 3] = wv.w;
            }
        } else {
            // reconstruct v (fp32) from packed bf16 g_vtw (natural order)
            for (int idx = tid; idx < 2048; idx += 256) {
                int ch = idx >> 5, p = idx & 31;
                unsigned val = g_vtw[(size_t)(b * 64 + ch) * (NN / 2) + blockIdx.x * 32 + p];
                __nv_bfloat162 h = *reinterpret_cast<__nv_bfloat162*>(&val);
                As[2 * p][ch]     = __bfloat162float(h.x);
                As[2 * p + 1][ch] = __bfloat162float(h.y);
            }
            for (int rr = r0; rr < 64; rr += 16) {
                float4 wv = *(const float4*)&g_M[b * 4096 + rr * 64 + cg * 4];
                Ws[rr][cg * 4 + 0] = wv.x; Ws[rr][cg * 4 + 1] = wv.y;
                Ws[rr][cg * 4 + 2] = wv.z; Ws[rr][cg * 4 + 3] = wv.w;
            }
        }
        __syncthreads();
        #pragma unroll 8
        for (int c = 0; c < 64; c++) {
            float a[4], wv[4];
            #pragma unroll
            for (int i = 0; i < 4; i++) a[i]  = As[ty * 4 + i][c];
            #pragma unroll
            for (int j = 0; j < 4; j++) wv[j] = Ws[tx * 4 + j][c];
            #pragma unroll
            for (int i = 0; i < 4; i++)
                #pragma unroll
                for (int j = 0; j < 4; j++)
                    acc[i][j] += a[i] * wv[j];
        }
    }
    #pragma unroll
    for (int i = 0; i < 4; i++) {
        float4 o;
        o.x = acc[i][0] + b1[tx * 4 + 0];
        o.y = acc[i][1] + b1[tx * 4 + 1];
        o.z = acc[i][2] + b1[tx * 4 + 2];
        o.w = acc[i][3] + b1[tx * 4 + 3];
        *(float4*)&g_y[(size_t)(b * NN + p0 + ty * 4 + i) * 64 + tx * 4] = o;
    }
}

// =====================================================================
// K6: bilinear 2x upsample + residual, coalesced.
// grid (128, Bb), block 256
// =====================================================================
__global__ void k_upsample2(const float* __restrict__ x, float* __restrict__ out) {
    __shared__ float Y[2][64 * 66];
    int b = blockIdx.y, i = blockIdx.x;
    int tid = threadIdx.x;
    int p = i >> 1;
    int r0, r1; float wy0, wy1;
    if (i & 1) { r0 = p; r1 = (p + 1 < 64) ? p + 1 : 63; wy0 = 0.75f; wy1 = 0.25f; }
    else       { r0 = (p > 0) ? p - 1 : 0; r1 = p;       wy0 = 0.25f; wy1 = 0.75f; }

    const float* yb = g_y + (size_t)b * NN * 64;
    int rows[2] = {r0, r1};
    for (int e2 = tid; e2 < 4096; e2 += 256) {
        int rr  = e2 >> 11;
        int rem = e2 & 2047;
        int s   = rem >> 5;
        int c2  = rem & 31;
        float2 v = *(const float2*)&yb[((rows[rr] * 64 + s) * 64) + c2 * 2];
        *(float2*)&Y[rr][s * 66 + c2 * 2] = v;
    }
    __syncthreads();

    size_t obase = ((size_t)b * 64 * 128 + i) * 128;
    for (int e = tid; e < 8192; e += 256) {
        int c = e >> 7, j = e & 127;
        int q = j >> 1;
        int s0, s1; float wx0, wx1;
        if (j & 1) { s0 = q; s1 = (q + 1 < 64) ? q + 1 : 63; wx0 = 0.75f; wx1 = 0.25f; }
        else       { s0 = (q > 0) ? q - 1 : 0; s1 = q;       wx0 = 0.25f; wx1 = 0.75f; }
        float v = wy0 * (wx0 * Y[0][s0 * 66 + c] + wx1 * Y[0][s1 * 66 + c])
                + wy1 * (wx0 * Y[1][s0 * 66 + c] + wx1 * Y[1][s1 * 66 + c]);
        size_t oi = obase + (size_t)c * 16384 + j;
        out[oi] = v + x[oi];
    }
}

// =====================================================================
extern "C" void kernel_launch(void* const* d_in, const int* in_sizes, int n_in,
                              void* d_out, int out_size) {
    const float* x        = (const float*)d_in[0];
    const float* pm_gamma = (const float*)d_in[1];
    const float* pm_beta  = (const float*)d_in[2];
    const float* pm_w     = (const float*)d_in[3];
    const float* pm_b     = (const float*)d_in[4];
    const float* w2 = (const float*)d_in[5];
    const float* b2 = (const float*)d_in[6];
    const float* w3 = (const float*)d_in[7];
    const float* b3 = (const float*)d_in[8];
    const float* w4 = (const float*)d_in[9];
    const float* b4 = (const float*)d_in[10];
    const float* w5 = (const float*)d_in[11];
    const float* b5 = (const float*)d_in[12];
    const float* w6 = (const float*)d_in[13];
    const float* b6 = (const float*)d_in[14];
    const float* w1 = (const float*)d_in[15];
    const float* b1 = (const float*)d_in[16];
    float* out = (float*)d_out;

    const int merge_smem = (256 * 65 + 64 * 65) * 4;                  // 83200 B
    const int qkv_smem   = (64 * 68 + 64 * 65 + 64 * 65) * 4;         // 50688 B
    const int attn_smem  = (2 * 64 * SKW * 2 + 4 * 32 * SPW) * 4;     // 55296 B
    cudaFuncSetAttribute(k_merge_pml, cudaFuncAttributeMaxDynamicSharedMemorySize, merge_smem);
    cudaFuncSetAttribute(k_qkv5,      cudaFuncAttributeMaxDynamicSharedMemorySize, qkv_smem);
    cudaFuncSetAttribute(k_attn1_tc,  cudaFuncAttributeMaxDynamicSharedMemorySize, attn_smem);

    k_merge_pml  <<<dim3(64, Bb), 256, merge_smem>>>(x, pm_gamma, pm_beta, pm_w, pm_b);
    k_qkv5       <<<dim3(64, Bb), 256, qkv_smem>>>(w2, b2, w3, b3, w4, b4, w5, b5, w6, b6);
    k_sreduce    <<<dim3(16, Bb), 256>>>();
    k_attn1_tc   <<<dim3(32, Bb, NSPLIT), 128, attn_smem>>>();
    k_chsoftmax_M<<<Bb, 256>>>(w1);
    k_proj       <<<dim3(64, Bb), 256>>>(w1, b1);
    k_upsample2  <<<dim3(128, Bb), 256>>>(x, out);
}

// round 15
// speedup vs baseline: 1.1150x; 1.0867x over previous
#include <cuda_runtime.h>
#include <cuda_bf16.h>

#define Bb 4
#define Cc 64
#define NN 4096    // 64*64 merged positions
#define HH 128
#define WW 128
#define LOG2E 1.4426950408889634f

// -------- scratch (static device globals) --------
__device__ float    g_c1[Bb*NN*Cc];        // (B,N,64)
__device__ unsigned g_qw [Bb*NN*32];       // q*log2e bf16x2 words (natural ch order)
__device__ unsigned g_kw [Bb*NN*32];       // k bf16x2 words (natural ch order)
__device__ unsigned g_vtw[Bb*64*(NN/2)];   // v bf16x2 [b][ch][pos-pair] natural order
__device__ float    g_o1p[2*Bb*NN*Cc];     // split-KV unnormalized partial O
__device__ float    g_ml [2*Bb*NN*2];      // split-KV per-row (m, l), m in log2 units
__device__ float    g_y  [Bb*NN*Cc];       // pre-upsample output
__device__ float    g_spart[64*Bb*64*64];  // channel-attn partial scores per pos-tile
__device__ float    g_s2 [Bb*64*64];       // reduced channel-attn scores
__device__ float    g_M  [Bb*64*64];       // w1_right @ softmax(scores)

__device__ __forceinline__ unsigned pk2(float lo, float hi) {
    __nv_bfloat162 h = __floats2bfloat162_rn(lo, hi);
    return *reinterpret_cast<unsigned*>(&h);
}
__device__ __forceinline__ float ex2(float x) {
    float r;
    asm("ex2.approx.f32 %0, %1;" : "=f"(r) : "f"(x));
    return r;
}
__device__ __forceinline__ void mma_tf32(float c[4], const float a[4],
                                         float b0f, float b1f) {
    asm volatile(
        "mma.sync.aligned.m16n8k8.row.col.f32.tf32.tf32.f32 "
        "{%0,%1,%2,%3}, {%4,%5,%6,%7}, {%8,%9}, {%0,%1,%2,%3};"
        : "+f"(c[0]), "+f"(c[1]), "+f"(c[2]), "+f"(c[3])
        : "r"(__float_as_uint(a[0])), "r"(__float_as_uint(a[1])),
          "r"(__float_as_uint(a[2])), "r"(__float_as_uint(a[3])),
          "r"(__float_as_uint(b0f)), "r"(__float_as_uint(b1f)));
}

// =====================================================================
// K1: fused patch-merge + LayerNorm + pm linear (256->64)
// grid (hh=64, b=4), block 256
// =====================================================================
extern __shared__ float smM[];
__global__ void k_merge_pml(const float* __restrict__ x,
                            const float* __restrict__ gamma,
                            const float* __restrict__ beta,
                            const float* __restrict__ pm_w,
                            const float* __restrict__ pm_b) {
    float (*ts)[65] = (float(*)[65])smM;              // [256][65]
    float (*Ws)[65] = (float(*)[65])(smM + 256 * 65); // [64][65]
    __shared__ float s_mu[64], s_rs[64];
    int b = blockIdx.y, hh = blockIdx.x, tid = threadIdx.x;

    for (int e = tid; e < 8192; e += 256) {
        int c2 = e >> 6;
        int p  = e & 63;
        int dr = c2 >> 6;
        int ch = c2 & 63;
        float2 v = *(const float2*)&x[(((b * 64 + ch) * 128) + 2 * hh + dr) * 128 + 2 * p];
        ts[dr * 64 + ch][p]       = v.x;
        ts[dr * 64 + ch + 128][p] = v.y;
    }
    __syncthreads();

    int w = tid >> 5, lane = tid & 31;
    for (int p = w * 8; p < w * 8 + 8; p++) {
        float s = 0.f, ss = 0.f;
        for (int c = lane; c < 256; c += 32) {
            float v = ts[c][p];
            s += v; ss += v * v;
        }
        #pragma unroll
        for (int off = 16; off; off >>= 1) {
            s  += __shfl_xor_sync(0xffffffffu, s,  off);
            ss += __shfl_xor_sync(0xffffffffu, ss, off);
        }
        float mu  = s * (1.f / 256.f);
        float var = ss * (1.f / 256.f) - mu * mu;
        if (lane == 0) { s_mu[p] = mu; s_rs[p] = rsqrtf(var + 1e-5f); }
    }
    __syncthreads();

    for (int e = tid; e < 16384; e += 256) {
        int c = e >> 6, p = e & 63;
        ts[c][p] = (ts[c][p] - s_mu[p]) * s_rs[p] * gamma[c] + beta[c];
    }

    int tx = tid & 15, ty = tid >> 4;
    float acc[4][4] = {};
    for (int kc = 0; kc < 4; kc++) {
        __syncthreads();
        int cg = tid & 15, r0 = tid >> 4;
        for (int rr = r0; rr < 64; rr += 16) {
            float4 wv = *(const float4*)&pm_w[rr * 256 + kc * 64 + cg * 4];
            Ws[rr][cg * 4 + 0] = wv.x; Ws[rr][cg * 4 + 1] = wv.y;
            Ws[rr][cg * 4 + 2] = wv.z; Ws[rr][cg * 4 + 3] = wv.w;
        }
        __syncthreads();
        #pragma unroll 8
        for (int c = 0; c < 64; c++) {
            float a[4], wv[4];
            #pragma unroll
            for (int i = 0; i < 4; i++) a[i]  = ts[kc * 64 + c][ty * 4 + i];
            #pragma unroll
            for (int j = 0; j < 4; j++) wv[j] = Ws[tx * 4 + j][c];
            #pragma unroll
            for (int i = 0; i < 4; i++)
                #pragma unroll
                for (int j = 0; j < 4; j++)
                    acc[i][j] += a[i] * wv[j];
        }
    }
    #pragma unroll
    for (int i = 0; i < 4; i++) {
        float4 o;
        o.x = acc[i][0] + pm_b[tx * 4 + 0];
        o.y = acc[i][1] + pm_b[tx * 4 + 1];
        o.z = acc[i][2] + pm_b[tx * 4 + 2];
        o.w = acc[i][3] + pm_b[tx * 4 + 3];
        *(float4*)&g_c1[(size_t)(b * NN + hh * 64 + ty * 4 + i) * 64 + tx * 4] = o;
    }
}

// =====================================================================
// K2: 5 projections + channel-attn scores, ALL via tf32 mma m16n8k8.
// 8 warps: wq = w&3 -> pos block 16*wq; wn = w>>2 -> out half 32*wn.
// A = c1 in As[64][68] fp32; B = weight rows Ws[64][68] ([out][ch]).
// grid (ptile=64, b=4), block 256, dynamic smem
// =====================================================================
extern __shared__ float smQ[];
__global__ void k_qkv5(const float* __restrict__ w2, const float* __restrict__ b2,
                       const float* __restrict__ w3, const float* __restrict__ b3,
                       const float* __restrict__ w4, const float* __restrict__ b4,
                       const float* __restrict__ w5, const float* __restrict__ b5,
                       const float* __restrict__ w6, const float* __restrict__ b6) {
    float (*As)[68]  = (float(*)[68])smQ;                          // [64][68]
    float (*Ws)[68]  = (float(*)[68])(smQ + 64 * 68);              // [64][68]
    float (*Q2s)[65] = (float(*)[65])(smQ + 64 * 68 + 64 * 68);    // [64][65]
    int b  = blockIdx.y;
    int p0 = blockIdx.x * 64;
    int tid = threadIdx.x;
    int w  = tid >> 5, lane = tid & 31;
    int g  = lane >> 2, t = lane & 3;
    int wq = w & 3, wn = w >> 2;
    int cg = tid & 15, r0 = tid >> 4;

    for (int rr = r0; rr < 64; rr += 16)
        *(float4*)&As[rr][cg * 4] =
            *(const float4*)&g_c1[(size_t)(b * NN + p0 + rr) * 64 + cg * 4];

    const float* wps[5] = {w2, w3, w4, w5, w6};
    const float* bps[5] = {b2, b3, b4, b5, b6};

    int row1 = 16 * wq + g;          // pos rows this thread owns
    int row2 = row1 + 8;

    for (int wi = 0; wi < 5; wi++) {
        __syncthreads();
        const float* wp = wps[wi];
        for (int rr = r0; rr < 64; rr += 16)
            *(float4*)&Ws[rr][cg * 4] = *(const float4*)&wp[rr * 64 + cg * 4];
        __syncthreads();

        // ---- GEMM: out[pos][o] = sum_ch c1[pos][ch] * w[o][ch] ----
        float acc[4][4] = {};
        #pragma unroll
        for (int ka = 0; ka < 8; ka++) {
            float a[4];
            a[0] = As[row1][8 * ka + t];
            a[1] = As[row2][8 * ka + t];
            a[2] = As[row1][8 * ka + t + 4];
            a[3] = As[row2][8 * ka + t + 4];
            #pragma unroll
            for (int nb = 0; nb < 4; nb++) {
                float b0 = Ws[32 * wn + 8 * nb + g][8 * ka + t];
                float b1 = Ws[32 * wn + 8 * nb + g][8 * ka + t + 4];
                mma_tf32(acc[nb], a, b0, b1);
            }
        }

        const float* bp = bps[wi];
        if (wi == 0 || wi == 1) {       // q (scaled by log2e) / k -> bf16 words
            float sc = (wi == 0) ? LOG2E : 1.f;
            unsigned* dst = (wi == 0) ? g_qw : g_kw;
            #pragma unroll
            for (int nb = 0; nb < 4; nb++) {
                int col = 32 * wn + 8 * nb + 2 * t;
                int wd  = 16 * wn + 4 * nb + t;
                dst[(size_t)(b * NN + p0 + row1) * 32 + wd] =
                    pk2((acc[nb][0] + bp[col]) * sc, (acc[nb][1] + bp[col + 1]) * sc);
                dst[(size_t)(b * NN + p0 + row2) * 32 + wd] =
                    pk2((acc[nb][2] + bp[col]) * sc, (acc[nb][3] + bp[col + 1]) * sc);
            }
        } else if (wi == 2) {           // v -> stage [ch][pos], then g_vtw
            #pragma unroll
            for (int nb = 0; nb < 4; nb++) {
                int col = 32 * wn + 8 * nb + 2 * t;
                Q2s[col][row1]     = acc[nb][0] + bp[col];
                Q2s[col + 1][row1] = acc[nb][1] + bp[col + 1];
                Q2s[col][row2]     = acc[nb][2] + bp[col];
                Q2s[col + 1][row2] = acc[nb][3] + bp[col + 1];
            }
            __syncthreads();
            for (int idx = tid; idx < 2048; idx += 256) {
                int ch = idx >> 5, wv = idx & 31;
                g_vtw[(size_t)(b * 64 + ch) * (NN / 2) + blockIdx.x * 32 + wv] =
                    pk2(Q2s[ch][2 * wv], Q2s[ch][2 * wv + 1]);
            }
        } else if (wi == 3) {           // q2 -> Q2s[pos][ch]
            #pragma unroll
            for (int nb = 0; nb < 4; nb++) {
                int col = 32 * wn + 8 * nb + 2 * t;
                Q2s[row1][col]     = acc[nb][0] + bp[col];
                Q2s[row1][col + 1] = acc[nb][1] + bp[col + 1];
                Q2s[row2][col]     = acc[nb][2] + bp[col];
                Q2s[row2][col + 1] = acc[nb][3] + bp[col + 1];
            }
        } else {                        // k2 -> As[pos][ch] (c1 no longer needed)
            __syncthreads();            // all warps done reading As
            #pragma unroll
            for (int nb = 0; nb < 4; nb++) {
                int col = 32 * wn + 8 * nb + 2 * t;
                As[row1][col]     = acc[nb][0] + bp[col];
                As[row1][col + 1] = acc[nb][1] + bp[col + 1];
                As[row2][col]     = acc[nb][2] + bp[col];
                As[row2][col + 1] = acc[nb][3] + bp[col + 1];
            }
            __syncthreads();

            // ---- scores: s2[c][d] = sum_pos q2[pos][c] * k2[pos][d] ----
            float a2[4][4] = {};
            #pragma unroll
            for (int ka = 0; ka < 8; ka++) {
                float a[4];
                a[0] = Q2s[8 * ka + t][row1];
                a[1] = Q2s[8 * ka + t][row2];
                a[2] = Q2s[8 * ka + t + 4][row1];
                a[3] = Q2s[8 * ka + t + 4][row2];
                #pragma unroll
                for (int nb = 0; nb < 4; nb++) {
                    int d = 32 * wn + 8 * nb + g;
                    float b0 = As[8 * ka + t][d];
                    float b1 = As[8 * ka + t + 4][d];
                    mma_tf32(a2[nb], a, b0, b1);
                }
            }
            float* dst = &g_spart[(size_t)blockIdx.x * Bb * 4096 + b * 4096];
            #pragma unroll
            for (int nb = 0; nb < 4; nb++) {
                int d = 32 * wn + 8 * nb + 2 * t;
                *(float2*)&dst[row1 * 64 + d] = make_float2(a2[nb][0], a2[nb][1]);
                *(float2*)&dst[row2 * 64 + d] = make_float2(a2[nb][2], a2[nb][3]);
            }
        }
    }
}

// =====================================================================
// K3: flash attention, bf16 mma m16n8k16, split-KV x2, exp2 softmax,
// ldmatrix.x4 fragment loads (unchanged from R14 best).
// =====================================================================
__device__ __forceinline__ void mma_bf16(float c[4], const unsigned a[4],
                                         unsigned b0, unsigned b1) {
    asm volatile(
        "mma.sync.aligned.m16n8k16.row.col.f32.bf16.bf16.f32 "
        "{%0,%1,%2,%3}, {%4,%5,%6,%7}, {%8,%9}, {%0,%1,%2,%3};"
        : "+f"(c[0]), "+f"(c[1]), "+f"(c[2]), "+f"(c[3])
        : "r"(a[0]), "r"(a[1]), "r"(a[2]), "r"(a[3]), "r"(b0), "r"(b1));
}
__device__ __forceinline__ void ldsm_x4(unsigned& r0, unsigned& r1,
                                        unsigned& r2, unsigned& r3, unsigned addr) {
    asm volatile("ldmatrix.sync.aligned.m8n8.x4.shared.b16 {%0,%1,%2,%3}, [%4];"
        : "=r"(r0), "=r"(r1), "=r"(r2), "=r"(r3) : "r"(addr));
}
__device__ __forceinline__ unsigned su32(const void* p) {
    return (unsigned)__cvta_generic_to_shared(p);
}

#define SKW 36     // K/V smem row stride (u32 words)
#define SPW 36     // P row stride (u32 words)
#define NSPLIT 2
#define ITERS (64 / NSPLIT)

extern __shared__ unsigned smAu[];
__global__ void __launch_bounds__(128) k_attn1_tc() {
    unsigned* Kb = smAu;                     // [2][64*SKW]
    unsigned* Vb = Kb + 2 * 64 * SKW;        // [2][64*SKW]
    unsigned* Pw = Vb + 2 * 64 * SKW;        // 4 warps * [32*SPW]

    int b   = blockIdx.y;
    int sp  = blockIdx.z;
    int m0  = blockIdx.x * 128;
    int tid = threadIdx.x;
    int w   = tid >> 5, lane = tid & 31;
    int g   = lane >> 2, t = lane & 3;
    int mm  = lane >> 3, rr8 = lane & 7;
    int bn_add = ((mm >> 1) << 3) + rr8;
    int bk_add = (mm & 1) << 2;
    int pm_add = ((mm & 1) << 3) + rr8;
    int pk_add = (mm >> 1) << 2;

    const unsigned* Qu = g_qw + (size_t)(b * NN + m0) * 32;
    const unsigned* Kg = g_kw + (size_t)b * NN * 32;
    const unsigned* Vg = g_vtw + (size_t)b * 64 * (NN / 2);
    int it0 = sp * ITERS;

    for (int s = 0; s < 2; s++) {
        const unsigned* kp = Kg + (size_t)(it0 + s) * 64 * 32;
        unsigned* kd = Kb + s * 64 * SKW;
        unsigned* vd = Vb + s * 64 * SKW;
        for (int idx = tid; idx < 512; idx += 128) {
            int r = idx >> 3, c = idx & 7;
            asm volatile("cp.async.cg.shared.global [%0], [%1], 16;" ::
                "r"(su32(kd + r * SKW + c * 4)), "l"(kp + r * 32 + c * 4));
            asm volatile("cp.async.cg.shared.global [%0], [%1], 16;" ::
                "r"(su32(vd + r * SKW + c * 4)),
                "l"(Vg + (size_t)r * (NN / 2) + (size_t)(it0 + s) * 32 + c * 4));
        }
        asm volatile("cp.async.commit_group;");
    }

    unsigned qf[2][4][4];
    #pragma unroll
    for (int rb = 0; rb < 2; rb++) {
        int r1 = 32 * w + 16 * rb + g;
        #pragma unroll
        for (int ka = 0; ka < 4; ka++) {
            qf[rb][ka][0] = Qu[r1 * 32 + 8 * ka + t];
            qf[rb][ka][1] = Qu[(r1 + 8) * 32 + 8 * ka + t];
            qf[rb][ka][2] = Qu[r1 * 32 + 8 * ka + t + 4];
            qf[rb][ka][3] = Qu[(r1 + 8) * 32 + 8 * ka + t + 4];
        }
    }

    unsigned* Pme = Pw + w * 32 * SPW;
    unsigned pme_base = su32(Pme);

    float O[2][8][4] = {};
    float mx[2][2], ls[2][2];
    #pragma unroll
    for (int rb = 0; rb < 2; rb++) {
        mx[rb][0] = mx[rb][1] = -1e30f;
        ls[rb][0] = ls[rb][1] = 0.f;
    }

    for (int j = 0; j < ITERS; j++) {
        asm volatile("cp.async.wait_group 1;" ::: "memory");
        __syncthreads();
        unsigned ks_base = su32(Kb + (j & 1) * 64 * SKW);
        unsigned vs_base = su32(Vb + (j & 1) * 64 * SKW);

        float S[2][8][4] = {};
        #pragma unroll
        for (int ka = 0; ka < 4; ka++) {
            #pragma unroll
            for (int np = 0; np < 4; np++) {
                unsigned b00, b01, b10, b11;
                ldsm_x4(b00, b01, b10, b11,
                        ks_base + (((16 * np + bn_add) * SKW + 8 * ka + bk_add) << 2));
                mma_bf16(S[0][2 * np],     qf[0][ka], b00, b01);
                mma_bf16(S[1][2 * np],     qf[1][ka], b00, b01);
                mma_bf16(S[0][2 * np + 1], qf[0][ka], b10, b11);
                mma_bf16(S[1][2 * np + 1], qf[1][ka], b10, b11);
            }
        }

        #pragma unroll
        for (int rb = 0; rb < 2; rb++) {
            float tm1 = -1e30f, tm2 = -1e30f;
            #pragma unroll
            for (int na = 0; na < 8; na++) {
                tm1 = fmaxf(tm1, fmaxf(S[rb][na][0], S[rb][na][1]));
                tm2 = fmaxf(tm2, fmaxf(S[rb][na][2], S[rb][na][3]));
            }
            tm1 = fmaxf(tm1, __shfl_xor_sync(0xffffffffu, tm1, 1));
            tm1 = fmaxf(tm1, __shfl_xor_sync(0xffffffffu, tm1, 2));
            tm2 = fmaxf(tm2, __shfl_xor_sync(0xffffffffu, tm2, 1));
            tm2 = fmaxf(tm2, __shfl_xor_sync(0xffffffffu, tm2, 2));

            float mn1 = fmaxf(mx[rb][0], tm1), mn2 = fmaxf(mx[rb][1], tm2);
            float a1 = ex2(mx[rb][0] - mn1), a2 = ex2(mx[rb][1] - mn2);
            mx[rb][0] = mn1; mx[rb][1] = mn2;

            float rs1 = 0.f, rs2 = 0.f;
            int rowA = (16 * rb + g) * SPW, rowB = (16 * rb + 8 + g) * SPW;
            #pragma unroll
            for (int na = 0; na < 8; na++) {
                float p0 = ex2(S[rb][na][0] - mn1);
                float p1 = ex2(S[rb][na][1] - mn1);
                float p2 = ex2(S[rb][na][2] - mn2);
                float p3 = ex2(S[rb][na][3] - mn2);
                rs1 += p0 + p1; rs2 += p2 + p3;
                Pme[rowA + 4 * na + t] = pk2(p0, p1);
                Pme[rowB + 4 * na + t] = pk2(p2, p3);
            }
            rs1 += __shfl_xor_sync(0xffffffffu, rs1, 1);
            rs1 += __shfl_xor_sync(0xffffffffu, rs1, 2);
            rs2 += __shfl_xor_sync(0xffffffffu, rs2, 1);
            rs2 += __shfl_xor_sync(0xffffffffu, rs2, 2);
            ls[rb][0] = ls[rb][0] * a1 + rs1;
            ls[rb][1] = ls[rb][1] * a2 + rs2;
            #pragma unroll
            for (int na = 0; na < 8; na++) {
                O[rb][na][0] *= a1; O[rb][na][1] *= a1;
                O[rb][na][2] *= a2; O[rb][na][3] *= a2;
            }
        }
        __syncwarp();

        #pragma unroll
        for (int ka = 0; ka < 4; ka++) {
            unsigned pa0[4], pa1[4];
            ldsm_x4(pa0[0], pa0[1], pa0[2], pa0[3],
                    pme_base + ((pm_add * SPW + 8 * ka + pk_add) << 2));
            ldsm_x4(pa1[0], pa1[1], pa1[2], pa1[3],
                    pme_base + (((16 + pm_add) * SPW + 8 * ka + pk_add) << 2));
            #pragma unroll
            for (int np = 0; np < 4; np++) {
                unsigned v00, v01, v10, v11;
                ldsm_x4(v00, v01, v10, v11,
                        vs_base + (((16 * np + bn_add) * SKW + 8 * ka + bk_add) << 2));
                mma_bf16(O[0][2 * np],     pa0, v00, v01);
                mma_bf16(O[1][2 * np],     pa1, v00, v01);
                mma_bf16(O[0][2 * np + 1], pa0, v10, v11);
                mma_bf16(O[1][2 * np + 1], pa1, v10, v11);
            }
        }
        __syncthreads();

        int nt = j + 2;
        if (nt < ITERS) {
            const unsigned* kp = Kg + (size_t)(it0 + nt) * 64 * 32;
            unsigned* kd = Kb + (nt & 1) * 64 * SKW;
            unsigned* vd = Vb + (nt & 1) * 64 * SKW;
            for (int idx = tid; idx < 512; idx += 128) {
                int r = idx >> 3, c = idx & 7;
                asm volatile("cp.async.cg.shared.global [%0], [%1], 16;" ::
                    "r"(su32(kd + r * SKW + c * 4)), "l"(kp + r * 32 + c * 4));
                asm volatile("cp.async.cg.shared.global [%0], [%1], 16;" ::
                    "r"(su32(vd + r * SKW + c * 4)),
                    "l"(Vg + (size_t)r * (NN / 2) + (size_t)(it0 + nt) * 32 + c * 4));
            }
        }
        asm volatile("cp.async.commit_group;");
    }

    float* Og = g_o1p + (size_t)(sp * Bb + b) * NN * 64;
    #pragma unroll
    for (int rb = 0; rb < 2; rb++) {
        int r1 = m0 + 32 * w + 16 * rb + g, r2 = r1 + 8;
        #pragma unroll
        for (int na = 0; na < 8; na++) {
            *(float2*)&Og[(size_t)r1 * 64 + 8 * na + 2 * t] =
                make_float2(O[rb][na][0], O[rb][na][1]);
            *(float2*)&Og[(size_t)r2 * 64 + 8 * na + 2 * t] =
                make_float2(O[rb][na][2], O[rb][na][3]);
        }
    }
    if (t == 0) {
        size_t base = (size_t)(sp * Bb + b) * NN + m0 + 32 * w;
        *(float2*)&g_ml[(base + g) * 2]      = make_float2(mx[0][0], ls[0][0]);
        *(float2*)&g_ml[(base + 8 + g) * 2]  = make_float2(mx[0][1], ls[0][1]);
        *(float2*)&g_ml[(base + 16 + g) * 2] = make_float2(mx[1][0], ls[1][0]);
        *(float2*)&g_ml[(base + 24 + g) * 2] = make_float2(mx[1][1], ls[1][1]);
    }
}

// =====================================================================
// K4a: parallel reduce of channel-attn partials: g_spart -> g_s2
// grid (16, Bb), block 256
// =====================================================================
__global__ void k_sreduce() {
    int b = blockIdx.y;
    int e = blockIdx.x * 256 + threadIdx.x;
    const float* src = g_spart + (size_t)b * 4096 + e;
    float s0 = 0.f, s1 = 0.f, s2 = 0.f, s3 = 0.f;
    #pragma unroll 4
    for (int t = 0; t < 64; t += 4) {
        s0 += src[(size_t)(t + 0) * Bb * 4096];
        s1 += src[(size_t)(t + 1) * Bb * 4096];
        s2 += src[(size_t)(t + 2) * Bb * 4096];
        s3 += src[(size_t)(t + 3) * Bb * 4096];
    }
    g_s2[b * 4096 + e] = (s0 + s1) + (s2 + s3);
}

// =====================================================================
// K4b: softmax over d + M = w1_right @ softmax.  grid: b=4
// =====================================================================
__global__ void k_chsoftmax_M(const float* __restrict__ w1) {
    __shared__ float s2s[64][65];
    int b = blockIdx.x;
    int tid = threadIdx.x;

    for (int e4 = tid; e4 < 1024; e4 += 256) {
        float4 v = *(const float4*)&g_s2[b * 4096 + e4 * 4];
        int e = e4 * 4, r = e >> 6, c = e & 63;
        s2s[r][c] = v.x; s2s[r][c + 1] = v.y; s2s[r][c + 2] = v.z; s2s[r][c + 3] = v.w;
    }
    __syncthreads();

    int w = tid >> 5, lane = tid & 31;
    for (int r = w; r < 64; r += 8) {
        float v0 = s2s[r][lane];
        float v1 = s2s[r][lane + 32];
        float m = fmaxf(v0, v1);
        #pragma unroll
        for (int off = 16; off; off >>= 1)
            m = fmaxf(m, __shfl_xor_sync(0xffffffffu, m, off));
        float e0 = __expf(v0 - m), e1 = __expf(v1 - m);
        float s = e0 + e1;
        #pragma unroll
        for (int off = 16; off; off >>= 1)
            s += __shfl_xor_sync(0xffffffffu, s, off);
        float inv = 1.f / s;
        s2s[r][lane] = e0 * inv;
        s2s[r][lane + 32] = e1 * inv;
    }
    __syncthreads();

    int tx = tid & 15, ty = tid >> 4;
    float acc[4][4] = {};
    #pragma unroll 4
    for (int c = 0; c < 64; c++) {
        float wv[4], qv[4];
        #pragma unroll
        for (int i = 0; i < 4; i++) wv[i] = w1[(ty * 4 + i) * 128 + 64 + c];
        #pragma unroll
        for (int j = 0; j < 4; j++) qv[j] = s2s[c][tx * 4 + j];
        #pragma unroll
        for (int i = 0; i < 4; i++)
            #pragma unroll
            for (int j = 0; j < 4; j++)
                acc[i][j] += wv[i] * qv[j];
    }
    #pragma unroll
    for (int i = 0; i < 4; i++)
        #pragma unroll
        for (int j = 0; j < 4; j++)
            g_M[b * 4096 + (ty * 4 + i) * 64 + tx * 4 + j] = acc[i][j];
}

// =====================================================================
// K5: y = w1_left @ combine(o1 splits) + M @ v + b1
// =====================================================================
__global__ void k_proj(const float* __restrict__ w1, const float* __restrict__ b1) {
    __shared__ float As[64][68];
    __shared__ float Ws[64][65];
    __shared__ float cS[NSPLIT][64];
    int b  = blockIdx.y;
    int p0 = blockIdx.x * 64;
    int tid = threadIdx.x;
    int tx = tid & 15, ty = tid >> 4;
    float acc[4][4] = {};

    if (tid < 64) {
        int row = p0 + tid;
        float2 mlv[NSPLIT];
        float m = -1e30f;
        #pragma unroll
        for (int s = 0; s < NSPLIT; s++) {
            mlv[s] = *(const float2*)&g_ml[((size_t)(s * Bb + b) * NN + row) * 2];
            m = fmaxf(m, mlv[s].x);
        }
        float den = 0.f, co[NSPLIT];
        #pragma unroll
        for (int s = 0; s < NSPLIT; s++) {
            co[s] = ex2(mlv[s].x - m);
            den += co[s] * mlv[s].y;
        }
        float inv = 1.f / den;
        #pragma unroll
        for (int s = 0; s < NSPLIT; s++) cS[s][tid] = co[s] * inv;
    }

    for (int ph = 0; ph < 2; ph++) {
        __syncthreads();
        int cg = tid & 15, r0 = tid >> 4;
        if (ph == 0) {
            for (int rr = r0; rr < 64; rr += 16) {
                float s0 = 0.f, s1 = 0.f, s2 = 0.f, s3 = 0.f;
                #pragma unroll
                for (int s = 0; s < NSPLIT; s++) {
                    float4 o = *(const float4*)&g_o1p[((size_t)(s * Bb + b) * NN + p0 + rr) * 64 + cg * 4];
                    float cf = cS[s][rr];
                    s0 += cf * o.x; s1 += cf * o.y; s2 += cf * o.z; s3 += cf * o.w;
                }
                *(float4*)&As[rr][cg * 4] = make_float4(s0, s1, s2, s3);
                float4 wv = *(const float4*)&w1[rr * 128 + cg * 4];
                Ws[rr][cg * 4 + 0] = wv.x; Ws[rr][cg * 4 + 1] = wv.y;
                Ws[rr][cg * 4 + 2] = wv.z; Ws[rr][cg * 4 + 3] = wv.w;
            }
        } else {
            for (int idx = tid; idx < 2048; idx += 256) {
                int ch = idx >> 5, p = idx & 31;
                unsigned val = g_vtw[(size_t)(b * 64 + ch) * (NN / 2) + blockIdx.x * 32 + p];
                __nv_bfloat162 h = *reinterpret_cast<__nv_bfloat162*>(&val);
                As[2 * p][ch]     = __bfloat162float(h.x);
                As[2 * p + 1][ch] = __bfloat162float(h.y);
            }
            for (int rr = r0; rr < 64; rr += 16) {
                float4 wv = *(const float4*)&g_M[b * 4096 + rr * 64 + cg * 4];
                Ws[rr][cg * 4 + 0] = wv.x; Ws[rr][cg * 4 + 1] = wv.y;
                Ws[rr][cg * 4 + 2] = wv.z; Ws[rr][cg * 4 + 3] = wv.w;
            }
        }
        __syncthreads();
        #pragma unroll 8
        for (int c = 0; c < 64; c++) {
            float a[4], wv[4];
            #pragma unroll
            for (int i = 0; i < 4; i++) a[i]  = As[ty * 4 + i][c];
            #pragma unroll
            for (int j = 0; j < 4; j++) wv[j] = Ws[tx * 4 + j][c];
            #pragma unroll
            for (int i = 0; i < 4; i++)
                #pragma unroll
                for (int j = 0; j < 4; j++)
                    acc[i][j] += a[i] * wv[j];
        }
    }
    #pragma unroll
    for (int i = 0; i < 4; i++) {
        float4 o;
        o.x = acc[i][0] + b1[tx * 4 + 0];
        o.y = acc[i][1] + b1[tx * 4 + 1];
        o.z = acc[i][2] + b1[tx * 4 + 2];
        o.w = acc[i][3] + b1[tx * 4 + 3];
        *(float4*)&g_y[(size_t)(b * NN + p0 + ty * 4 + i) * 64 + tx * 4] = o;
    }
}

// =====================================================================
// K6: bilinear 2x upsample + residual, coalesced.
// grid (128, Bb), block 256
// =====================================================================
__global__ void k_upsample2(const float* __restrict__ x, float* __restrict__ out) {
    __shared__ float Y[2][64 * 66];
    int b = blockIdx.y, i = blockIdx.x;
    int tid = threadIdx.x;
    int p = i >> 1;
    int r0, r1; float wy0, wy1;
    if (i & 1) { r0 = p; r1 = (p + 1 < 64) ? p + 1 : 63; wy0 = 0.75f; wy1 = 0.25f; }
    else       { r0 = (p > 0) ? p - 1 : 0; r1 = p;       wy0 = 0.25f; wy1 = 0.75f; }

    const float* yb = g_y + (size_t)b * NN * 64;
    int rows[2] = {r0, r1};
    for (int e2 = tid; e2 < 4096; e2 += 256) {
        int rr  = e2 >> 11;
        int rem = e2 & 2047;
        int s   = rem >> 5;
        int c2  = rem & 31;
        float2 v = *(const float2*)&yb[((rows[rr] * 64 + s) * 64) + c2 * 2];
        *(float2*)&Y[rr][s * 66 + c2 * 2] = v;
    }
    __syncthreads();

    size_t obase = ((size_t)b * 64 * 128 + i) * 128;
    for (int e = tid; e < 8192; e += 256) {
        int c = e >> 7, j = e & 127;
        int q = j >> 1;
        int s0, s1; float wx0, wx1;
        if (j & 1) { s0 = q; s1 = (q + 1 < 64) ? q + 1 : 63; wx0 = 0.75f; wx1 = 0.25f; }
        else       { s0 = (q > 0) ? q - 1 : 0; s1 = q;       wx0 = 0.25f; wx1 = 0.75f; }
        float v = wy0 * (wx0 * Y[0][s0 * 66 + c] + wx1 * Y[0][s1 * 66 + c])
                + wy1 * (wx0 * Y[1][s0 * 66 + c] + wx1 * Y[1][s1 * 66 + c]);
        size_t oi = obase + (size_t)c * 16384 + j;
        out[oi] = v + x[oi];
    }
}

// =====================================================================
extern "C" void kernel_launch(void* const* d_in, const int* in_sizes, int n_in,
                              void* d_out, int out_size) {
    const float* x        = (const float*)d_in[0];
    const float* pm_gamma = (const float*)d_in[1];
    const float* pm_beta  = (const float*)d_in[2];
    const float* pm_w     = (const float*)d_in[3];
    const float* pm_b     = (const float*)d_in[4];
    const float* w2 = (const float*)d_in[5];
    const float* b2 = (const float*)d_in[6];
    const float* w3 = (const float*)d_in[7];
    const float* b3 = (const float*)d_in[8];
    const float* w4 = (const float*)d_in[9];
    const float* b4 = (const float*)d_in[10];
    const float* w5 = (const float*)d_in[11];
    const float* b5 = (const float*)d_in[12];
    const float* w6 = (const float*)d_in[13];
    const float* b6 = (const float*)d_in[14];
    const float* w1 = (const float*)d_in[15];
    const float* b1 = (const float*)d_in[16];
    float* out = (float*)d_out;

    const int merge_smem = (256 * 65 + 64 * 65) * 4;                  // 83200 B
    const int qkv_smem   = (64 * 68 + 64 * 68 + 64 * 65) * 4;         // 51456 B
    const int attn_smem  = (2 * 64 * SKW * 2 + 4 * 32 * SPW) * 4;     // 55296 B
    cudaFuncSetAttribute(k_merge_pml, cudaFuncAttributeMaxDynamicSharedMemorySize, merge_smem);
    cudaFuncSetAttribute(k_qkv5,      cudaFuncAttributeMaxDynamicSharedMemorySize, qkv_smem);
    cudaFuncSetAttribute(k_attn1_tc,  cudaFuncAttributeMaxDynamicSharedMemorySize, attn_smem);

    k_merge_pml  <<<dim3(64, Bb), 256, merge_smem>>>(x, pm_gamma, pm_beta, pm_w, pm_b);
    k_qkv5       <<<dim3(64, Bb), 256, qkv_smem>>>(w2, b2, w3, b3, w4, b4, w5, b5, w6, b6);
    k_sreduce    <<<dim3(16, Bb), 256>>>();
    k_attn1_tc   <<<dim3(32, Bb, NSPLIT), 128, attn_smem>>>();
    k_chsoftmax_M<<<Bb, 256>>>(w1);
    k_proj       <<<dim3(64, Bb), 256>>>(w1, b1);
    k_upsample2  <<<dim3(128, Bb), 256>>>(x, out);
}

// round 16
// speedup vs baseline: 1.2246x; 1.0983x over previous
#include <cuda_runtime.h>
#include <cuda_bf16.h>

#define Bb 4
#define Cc 64
#define NN 4096    // 64*64 merged positions
#define HH 128
#define WW 128
#define LOG2E 1.4426950408889634f

// -------- scratch (static device globals) --------
__device__ float    g_c1[Bb*NN*Cc];        // (B,N,64)
__device__ unsigned g_qw [Bb*NN*32];       // q*log2e bf16x2 words (natural ch order)
__device__ unsigned g_kw [Bb*NN*32];       // k bf16x2 words (natural ch order)
__device__ unsigned g_vtw[Bb*64*(NN/2)];   // v bf16x2 [b][ch][pos-pair] natural order
__device__ float    g_o1p[2*Bb*NN*Cc];     // split-KV unnormalized partial O
__device__ float    g_ml [2*Bb*NN*2];      // split-KV per-row (m, l), m in log2 units
__device__ float    g_y  [Bb*NN*Cc];       // pre-upsample output
__device__ float    g_spart[64*Bb*64*64];  // channel-attn partial scores per pos-tile
__device__ float    g_s2 [Bb*64*64];       // reduced channel-attn scores
__device__ float    g_M  [Bb*64*64];       // w1_right @ softmax(scores)

__device__ __forceinline__ unsigned pk2(float lo, float hi) {
    __nv_bfloat162 h = __floats2bfloat162_rn(lo, hi);
    return *reinterpret_cast<unsigned*>(&h);
}
__device__ __forceinline__ float ex2(float x) {
    float r;
    asm("ex2.approx.f32 %0, %1;" : "=f"(r) : "f"(x));
    return r;
}
__device__ __forceinline__ void mma_tf32(float c[4], const float a[4],
                                         float b0f, float b1f) {
    asm volatile(
        "mma.sync.aligned.m16n8k8.row.col.f32.tf32.tf32.f32 "
        "{%0,%1,%2,%3}, {%4,%5,%6,%7}, {%8,%9}, {%0,%1,%2,%3};"
        : "+f"(c[0]), "+f"(c[1]), "+f"(c[2]), "+f"(c[3])
        : "r"(__float_as_uint(a[0])), "r"(__float_as_uint(a[1])),
          "r"(__float_as_uint(a[2])), "r"(__float_as_uint(a[3])),
          "r"(__float_as_uint(b0f)), "r"(__float_as_uint(b1f)));
}

// =====================================================================
// K1: fused patch-merge + LayerNorm + pm linear (256->64), tf32 mma.
// x staged [pos][ch] stride 260 (≡4 mod 32 -> A-frags conflict-free).
// 8 warps: wq = w&3 -> pos block, wn = w>>2 -> out half.
// grid (hh=64, b=4), block 256
// =====================================================================
extern __shared__ float smM[];
__global__ void k_merge_pml(const float* __restrict__ x,
                            const float* __restrict__ gamma,
                            const float* __restrict__ beta,
                            const float* __restrict__ pm_w,
                            const float* __restrict__ pm_b) {
    float (*ts)[260] = (float(*)[260])smM;             // [64 pos][256 ch]
    float (*Ws)[68]  = (float(*)[68])(smM + 64 * 260); // [64 out][64 kchunk]
    __shared__ float s_mu[64], s_rs[64];
    int b = blockIdx.y, hh = blockIdx.x, tid = threadIdx.x;
    int w = tid >> 5, lane = tid & 31;
    int g = lane >> 2, t = lane & 3;
    int wq = w & 3, wn = w >> 2;
    int cg = tid & 15, r0 = tid >> 4;

    // stage x into [pos][ch] (ch = (dr + 2*dc)*64 + c)
    for (int e = tid; e < 8192; e += 256) {
        int c2 = e >> 6;          // dr*64 + ch
        int p  = e & 63;
        int dr = c2 >> 6;
        int ch = c2 & 63;
        float2 v = *(const float2*)&x[(((b * 64 + ch) * 128) + 2 * hh + dr) * 128 + 2 * p];
        ts[p][dr * 64 + ch]       = v.x;   // dc=0
        ts[p][128 + dr * 64 + ch] = v.y;   // dc=1
    }
    __syncthreads();

    // LN stats: warp w owns rows 8w..8w+7
    for (int r = w * 8; r < w * 8 + 8; r++) {
        float s = 0.f, ss = 0.f;
        #pragma unroll
        for (int c = lane; c < 256; c += 32) {
            float v = ts[r][c];
            s += v; ss += v * v;
        }
        #pragma unroll
        for (int off = 16; off; off >>= 1) {
            s  += __shfl_xor_sync(0xffffffffu, s,  off);
            ss += __shfl_xor_sync(0xffffffffu, ss, off);
        }
        float mu  = s * (1.f / 256.f);
        float var = ss * (1.f / 256.f) - mu * mu;
        if (lane == 0) { s_mu[r] = mu; s_rs[r] = rsqrtf(var + 1e-5f); }
    }
    __syncthreads();

    // normalize in place (row-major: conflict-free)
    for (int e = tid; e < 16384; e += 256) {
        int p = e >> 8, c = e & 255;
        ts[p][c] = (ts[p][c] - s_mu[p]) * s_rs[p] * gamma[c] + beta[c];
    }

    // tensor-core GEMM: out[pos][o] = sum_ch ts[pos][ch] * pm_w[o][ch]
    int row1 = 16 * wq + g, row2 = row1 + 8;
    float acc[4][4] = {};
    for (int kc = 0; kc < 4; kc++) {
        __syncthreads();
        for (int rr = r0; rr < 64; rr += 16)
            *(float4*)&Ws[rr][cg * 4] =
                *(const float4*)&pm_w[rr * 256 + kc * 64 + cg * 4];
        __syncthreads();
        #pragma unroll
        for (int ka = 0; ka < 8; ka++) {
            float a[4];
            a[0] = ts[row1][kc * 64 + 8 * ka + t];
            a[1] = ts[row2][kc * 64 + 8 * ka + t];
            a[2] = ts[row1][kc * 64 + 8 * ka + t + 4];
            a[3] = ts[row2][kc * 64 + 8 * ka + t + 4];
            #pragma unroll
            for (int nb = 0; nb < 4; nb++) {
                float b0 = Ws[32 * wn + 8 * nb + g][8 * ka + t];
                float b1 = Ws[32 * wn + 8 * nb + g][8 * ka + t + 4];
                mma_tf32(acc[nb], a, b0, b1);
            }
        }
    }
    #pragma unroll
    for (int nb = 0; nb < 4; nb++) {
        int col = 32 * wn + 8 * nb + 2 * t;
        *(float2*)&g_c1[(size_t)(b * NN + hh * 64 + row1) * 64 + col] =
            make_float2(acc[nb][0] + pm_b[col], acc[nb][1] + pm_b[col + 1]);
        *(float2*)&g_c1[(size_t)(b * NN + hh * 64 + row2) * 64 + col] =
            make_float2(acc[nb][2] + pm_b[col], acc[nb][3] + pm_b[col + 1]);
    }
}

// =====================================================================
// K2: 5 projections + channel-attn scores, ALL via tf32 mma m16n8k8.
// grid (ptile=64, b=4), block 256, dynamic smem
// =====================================================================
extern __shared__ float smQ[];
__global__ void k_qkv5(const float* __restrict__ w2, const float* __restrict__ b2,
                       const float* __restrict__ w3, const float* __restrict__ b3,
                       const float* __restrict__ w4, const float* __restrict__ b4,
                       const float* __restrict__ w5, const float* __restrict__ b5,
                       const float* __restrict__ w6, const float* __restrict__ b6) {
    float (*As)[68]  = (float(*)[68])smQ;                          // [64][68]
    float (*Ws)[68]  = (float(*)[68])(smQ + 64 * 68);              // [64][68]
    float (*Q2s)[65] = (float(*)[65])(smQ + 64 * 68 + 64 * 68);    // [64][65]
    int b  = blockIdx.y;
    int p0 = blockIdx.x * 64;
    int tid = threadIdx.x;
    int w  = tid >> 5, lane = tid & 31;
    int g  = lane >> 2, t = lane & 3;
    int wq = w & 3, wn = w >> 2;
    int cg = tid & 15, r0 = tid >> 4;

    for (int rr = r0; rr < 64; rr += 16)
        *(float4*)&As[rr][cg * 4] =
            *(const float4*)&g_c1[(size_t)(b * NN + p0 + rr) * 64 + cg * 4];

    const float* wps[5] = {w2, w3, w4, w5, w6};
    const float* bps[5] = {b2, b3, b4, b5, b6};

    int row1 = 16 * wq + g;
    int row2 = row1 + 8;

    for (int wi = 0; wi < 5; wi++) {
        __syncthreads();
        const float* wp = wps[wi];
        for (int rr = r0; rr < 64; rr += 16)
            *(float4*)&Ws[rr][cg * 4] = *(const float4*)&wp[rr * 64 + cg * 4];
        __syncthreads();

        float acc[4][4] = {};
        #pragma unroll
        for (int ka = 0; ka < 8; ka++) {
            float a[4];
            a[0] = As[row1][8 * ka + t];
            a[1] = As[row2][8 * ka + t];
            a[2] = As[row1][8 * ka + t + 4];
            a[3] = As[row2][8 * ka + t + 4];
            #pragma unroll
            for (int nb = 0; nb < 4; nb++) {
                float b0 = Ws[32 * wn + 8 * nb + g][8 * ka + t];
                float b1 = Ws[32 * wn + 8 * nb + g][8 * ka + t + 4];
                mma_tf32(acc[nb], a, b0, b1);
            }
        }

        const float* bp = bps[wi];
        if (wi == 0 || wi == 1) {       // q (scaled by log2e) / k -> bf16 words
            float sc = (wi == 0) ? LOG2E : 1.f;
            unsigned* dst = (wi == 0) ? g_qw : g_kw;
            #pragma unroll
            for (int nb = 0; nb < 4; nb++) {
                int col = 32 * wn + 8 * nb + 2 * t;
                int wd  = 16 * wn + 4 * nb + t;
                dst[(size_t)(b * NN + p0 + row1) * 32 + wd] =
                    pk2((acc[nb][0] + bp[col]) * sc, (acc[nb][1] + bp[col + 1]) * sc);
                dst[(size_t)(b * NN + p0 + row2) * 32 + wd] =
                    pk2((acc[nb][2] + bp[col]) * sc, (acc[nb][3] + bp[col + 1]) * sc);
            }
        } else if (wi == 2) {           // v -> stage [ch][pos], then g_vtw
            #pragma unroll
            for (int nb = 0; nb < 4; nb++) {
                int col = 32 * wn + 8 * nb + 2 * t;
                Q2s[col][row1]     = acc[nb][0] + bp[col];
                Q2s[col + 1][row1] = acc[nb][1] + bp[col + 1];
                Q2s[col][row2]     = acc[nb][2] + bp[col];
                Q2s[col + 1][row2] = acc[nb][3] + bp[col + 1];
            }
            __syncthreads();
            for (int idx = tid; idx < 2048; idx += 256) {
                int ch = idx >> 5, wv = idx & 31;
                g_vtw[(size_t)(b * 64 + ch) * (NN / 2) + blockIdx.x * 32 + wv] =
                    pk2(Q2s[ch][2 * wv], Q2s[ch][2 * wv + 1]);
            }
        } else if (wi == 3) {           // q2 -> Q2s[pos][ch]
            #pragma unroll
            for (int nb = 0; nb < 4; nb++) {
                int col = 32 * wn + 8 * nb + 2 * t;
                Q2s[row1][col]     = acc[nb][0] + bp[col];
                Q2s[row1][col + 1] = acc[nb][1] + bp[col + 1];
                Q2s[row2][col]     = acc[nb][2] + bp[col];
                Q2s[row2][col + 1] = acc[nb][3] + bp[col + 1];
            }
        } else {                        // k2 -> As[pos][ch]
            __syncthreads();
            #pragma unroll
            for (int nb = 0; nb < 4; nb++) {
                int col = 32 * wn + 8 * nb + 2 * t;
                As[row1][col]     = acc[nb][0] + bp[col];
                As[row1][col + 1] = acc[nb][1] + bp[col + 1];
                As[row2][col]     = acc[nb][2] + bp[col];
                As[row2][col + 1] = acc[nb][3] + bp[col + 1];
            }
            __syncthreads();

            // scores: s2[c][d] = sum_pos q2[pos][c] * k2[pos][d]
            float a2[4][4] = {};
            #pragma unroll
            for (int ka = 0; ka < 8; ka++) {
                float a[4];
                a[0] = Q2s[8 * ka + t][row1];
                a[1] = Q2s[8 * ka + t][row2];
                a[2] = Q2s[8 * ka + t + 4][row1];
                a[3] = Q2s[8 * ka + t + 4][row2];
                #pragma unroll
                for (int nb = 0; nb < 4; nb++) {
                    int d = 32 * wn + 8 * nb + g;
                    float b0 = As[8 * ka + t][d];
                    float b1 = As[8 * ka + t + 4][d];
                    mma_tf32(a2[nb], a, b0, b1);
                }
            }
            float* dst = &g_spart[(size_t)blockIdx.x * Bb * 4096 + b * 4096];
            #pragma unroll
            for (int nb = 0; nb < 4; nb++) {
                int d = 32 * wn + 8 * nb + 2 * t;
                *(float2*)&dst[row1 * 64 + d] = make_float2(a2[nb][0], a2[nb][1]);
                *(float2*)&dst[row2 * 64 + d] = make_float2(a2[nb][2], a2[nb][3]);
            }
        }
    }
}

// =====================================================================
// K3: flash attention, bf16 mma m16n8k16, split-KV x2, exp2 softmax,
// ldmatrix.x4 fragment loads (unchanged).
// =====================================================================
__device__ __forceinline__ void mma_bf16(float c[4], const unsigned a[4],
                                         unsigned b0, unsigned b1) {
    asm volatile(
        "mma.sync.aligned.m16n8k16.row.col.f32.bf16.bf16.f32 "
        "{%0,%1,%2,%3}, {%4,%5,%6,%7}, {%8,%9}, {%0,%1,%2,%3};"
        : "+f"(c[0]), "+f"(c[1]), "+f"(c[2]), "+f"(c[3])
        : "r"(a[0]), "r"(a[1]), "r"(a[2]), "r"(a[3]), "r"(b0), "r"(b1));
}
__device__ __forceinline__ void ldsm_x4(unsigned& r0, unsigned& r1,
                                        unsigned& r2, unsigned& r3, unsigned addr) {
    asm volatile("ldmatrix.sync.aligned.m8n8.x4.shared.b16 {%0,%1,%2,%3}, [%4];"
        : "=r"(r0), "=r"(r1), "=r"(r2), "=r"(r3) : "r"(addr));
}
__device__ __forceinline__ unsigned su32(const void* p) {
    return (unsigned)__cvta_generic_to_shared(p);
}

#define SKW 36     // K/V smem row stride (u32 words)
#define SPW 36     // P row stride (u32 words)
#define NSPLIT 2
#define ITERS (64 / NSPLIT)

extern __shared__ unsigned smAu[];
__global__ void __launch_bounds__(128) k_attn1_tc() {
    unsigned* Kb = smAu;                     // [2][64*SKW]
    unsigned* Vb = Kb + 2 * 64 * SKW;        // [2][64*SKW]
    unsigned* Pw = Vb + 2 * 64 * SKW;        // 4 warps * [32*SPW]

    int b   = blockIdx.y;
    int sp  = blockIdx.z;
    int m0  = blockIdx.x * 128;
    int tid = threadIdx.x;
    int w   = tid >> 5, lane = tid & 31;
    int g   = lane >> 2, t = lane & 3;
    int mm  = lane >> 3, rr8 = lane & 7;
    int bn_add = ((mm >> 1) << 3) + rr8;
    int bk_add = (mm & 1) << 2;
    int pm_add = ((mm & 1) << 3) + rr8;
    int pk_add = (mm >> 1) << 2;

    const unsigned* Qu = g_qw + (size_t)(b * NN + m0) * 32;
    const unsigned* Kg = g_kw + (size_t)b * NN * 32;
    const unsigned* Vg = g_vtw + (size_t)b * 64 * (NN / 2);
    int it0 = sp * ITERS;

    for (int s = 0; s < 2; s++) {
        const unsigned* kp = Kg + (size_t)(it0 + s) * 64 * 32;
        unsigned* kd = Kb + s * 64 * SKW;
        unsigned* vd = Vb + s * 64 * SKW;
        for (int idx = tid; idx < 512; idx += 128) {
            int r = idx >> 3, c = idx & 7;
            asm volatile("cp.async.cg.shared.global [%0], [%1], 16;" ::
                "r"(su32(kd + r * SKW + c * 4)), "l"(kp + r * 32 + c * 4));
            asm volatile("cp.async.cg.shared.global [%0], [%1], 16;" ::
                "r"(su32(vd + r * SKW + c * 4)),
                "l"(Vg + (size_t)r * (NN / 2) + (size_t)(it0 + s) * 32 + c * 4));
        }
        asm volatile("cp.async.commit_group;");
    }

    unsigned qf[2][4][4];
    #pragma unroll
    for (int rb = 0; rb < 2; rb++) {
        int r1 = 32 * w + 16 * rb + g;
        #pragma unroll
        for (int ka = 0; ka < 4; ka++) {
            qf[rb][ka][0] = Qu[r1 * 32 + 8 * ka + t];
            qf[rb][ka][1] = Qu[(r1 + 8) * 32 + 8 * ka + t];
            qf[rb][ka][2] = Qu[r1 * 32 + 8 * ka + t + 4];
            qf[rb][ka][3] = Qu[(r1 + 8) * 32 + 8 * ka + t + 4];
        }
    }

    unsigned* Pme = Pw + w * 32 * SPW;
    unsigned pme_base = su32(Pme);

    float O[2][8][4] = {};
    float mx[2][2], ls[2][2];
    #pragma unroll
    for (int rb = 0; rb < 2; rb++) {
        mx[rb][0] = mx[rb][1] = -1e30f;
        ls[rb][0] = ls[rb][1] = 0.f;
    }

    for (int j = 0; j < ITERS; j++) {
        asm volatile("cp.async.wait_group 1;" ::: "memory");
        __syncthreads();
        unsigned ks_base = su32(Kb + (j & 1) * 64 * SKW);
        unsigned vs_base = su32(Vb + (j & 1) * 64 * SKW);

        float S[2][8][4] = {};
        #pragma unroll
        for (int ka = 0; ka < 4; ka++) {
            #pragma unroll
            for (int np = 0; np < 4; np++) {
                unsigned b00, b01, b10, b11;
                ldsm_x4(b00, b01, b10, b11,
                        ks_base + (((16 * np + bn_add) * SKW + 8 * ka + bk_add) << 2));
                mma_bf16(S[0][2 * np],     qf[0][ka], b00, b01);
                mma_bf16(S[1][2 * np],     qf[1][ka], b00, b01);
                mma_bf16(S[0][2 * np + 1], qf[0][ka], b10, b11);
                mma_bf16(S[1][2 * np + 1], qf[1][ka], b10, b11);
            }
        }

        #pragma unroll
        for (int rb = 0; rb < 2; rb++) {
            float tm1 = -1e30f, tm2 = -1e30f;
            #pragma unroll
            for (int na = 0; na < 8; na++) {
                tm1 = fmaxf(tm1, fmaxf(S[rb][na][0], S[rb][na][1]));
                tm2 = fmaxf(tm2, fmaxf(S[rb][na][2], S[rb][na][3]));
            }
            tm1 = fmaxf(tm1, __shfl_xor_sync(0xffffffffu, tm1, 1));
            tm1 = fmaxf(tm1, __shfl_xor_sync(0xffffffffu, tm1, 2));
            tm2 = fmaxf(tm2, __shfl_xor_sync(0xffffffffu, tm2, 1));
            tm2 = fmaxf(tm2, __shfl_xor_sync(0xffffffffu, tm2, 2));

            float mn1 = fmaxf(mx[rb][0], tm1), mn2 = fmaxf(mx[rb][1], tm2);
            float a1 = ex2(mx[rb][0] - mn1), a2 = ex2(mx[rb][1] - mn2);
            mx[rb][0] = mn1; mx[rb][1] = mn2;

            float rs1 = 0.f, rs2 = 0.f;
            int rowA = (16 * rb + g) * SPW, rowB = (16 * rb + 8 + g) * SPW;
            #pragma unroll
            for (int na = 0; na < 8; na++) {
                float p0 = ex2(S[rb][na][0] - mn1);
                float p1 = ex2(S[rb][na][1] - mn1);
                float p2 = ex2(S[rb][na][2] - mn2);
                float p3 = ex2(S[rb][na][3] - mn2);
                rs1 += p0 + p1; rs2 += p2 + p3;
                Pme[rowA + 4 * na + t] = pk2(p0, p1);
                Pme[rowB + 4 * na + t] = pk2(p2, p3);
            }
            rs1 += __shfl_xor_sync(0xffffffffu, rs1, 1);
            rs1 += __shfl_xor_sync(0xffffffffu, rs1, 2);
            rs2 += __shfl_xor_sync(0xffffffffu, rs2, 1);
            rs2 += __shfl_xor_sync(0xffffffffu, rs2, 2);
            ls[rb][0] = ls[rb][0] * a1 + rs1;
            ls[rb][1] = ls[rb][1] * a2 + rs2;
            #pragma unroll
            for (int na = 0; na < 8; na++) {
                O[rb][na][0] *= a1; O[rb][na][1] *= a1;
                O[rb][na][2] *= a2; O[rb][na][3] *= a2;
            }
        }
        __syncwarp();

        #pragma unroll
        for (int ka = 0; ka < 4; ka++) {
            unsigned pa0[4], pa1[4];
            ldsm_x4(pa0[0], pa0[1], pa0[2], pa0[3],
                    pme_base + ((pm_add * SPW + 8 * ka + pk_add) << 2));
            ldsm_x4(pa1[0], pa1[1], pa1[2], pa1[3],
                    pme_base + (((16 + pm_add) * SPW + 8 * ka + pk_add) << 2));
            #pragma unroll
            for (int np = 0; np < 4; np++) {
                unsigned v00, v01, v10, v11;
                ldsm_x4(v00, v01, v10, v11,
                        vs_base + (((16 * np + bn_add) * SKW + 8 * ka + bk_add) << 2));
                mma_bf16(O[0][2 * np],     pa0, v00, v01);
                mma_bf16(O[1][2 * np],     pa1, v00, v01);
                mma_bf16(O[0][2 * np + 1], pa0, v10, v11);
                mma_bf16(O[1][2 * np + 1], pa1, v10, v11);
            }
        }
        __syncthreads();

        int nt = j + 2;
        if (nt < ITERS) {
            const unsigned* kp = Kg + (size_t)(it0 + nt) * 64 * 32;
            unsigned* kd = Kb + (nt & 1) * 64 * SKW;
            unsigned* vd = Vb + (nt & 1) * 64 * SKW;
            for (int idx = tid; idx < 512; idx += 128) {
                int r = idx >> 3, c = idx & 7;
                asm volatile("cp.async.cg.shared.global [%0], [%1], 16;" ::
                    "r"(su32(kd + r * SKW + c * 4)), "l"(kp + r * 32 + c * 4));
                asm volatile("cp.async.cg.shared.global [%0], [%1], 16;" ::
                    "r"(su32(vd + r * SKW + c * 4)),
                    "l"(Vg + (size_t)r * (NN / 2) + (size_t)(it0 + nt) * 32 + c * 4));
            }
        }
        asm volatile("cp.async.commit_group;");
    }

    float* Og = g_o1p + (size_t)(sp * Bb + b) * NN * 64;
    #pragma unroll
    for (int rb = 0; rb < 2; rb++) {
        int r1 = m0 + 32 * w + 16 * rb + g, r2 = r1 + 8;
        #pragma unroll
        for (int na = 0; na < 8; na++) {
            *(float2*)&Og[(size_t)r1 * 64 + 8 * na + 2 * t] =
                make_float2(O[rb][na][0], O[rb][na][1]);
            *(float2*)&Og[(size_t)r2 * 64 + 8 * na + 2 * t] =
                make_float2(O[rb][na][2], O[rb][na][3]);
        }
    }
    if (t == 0) {
        size_t base = (size_t)(sp * Bb + b) * NN + m0 + 32 * w;
        *(float2*)&g_ml[(base + g) * 2]      = make_float2(mx[0][0], ls[0][0]);
        *(float2*)&g_ml[(base + 8 + g) * 2]  = make_float2(mx[0][1], ls[0][1]);
        *(float2*)&g_ml[(base + 16 + g) * 2] = make_float2(mx[1][0], ls[1][0]);
        *(float2*)&g_ml[(base + 24 + g) * 2] = make_float2(mx[1][1], ls[1][1]);
    }
}

// =====================================================================
// K4a: parallel reduce of channel-attn partials: g_spart -> g_s2
// grid (16, Bb), block 256
// =====================================================================
__global__ void k_sreduce() {
    int b = blockIdx.y;
    int e = blockIdx.x * 256 + threadIdx.x;
    const float* src = g_spart + (size_t)b * 4096 + e;
    float s0 = 0.f, s1 = 0.f, s2 = 0.f, s3 = 0.f;
    #pragma unroll 4
    for (int t = 0; t < 64; t += 4) {
        s0 += src[(size_t)(t + 0) * Bb * 4096];
        s1 += src[(size_t)(t + 1) * Bb * 4096];
        s2 += src[(size_t)(t + 2) * Bb * 4096];
        s3 += src[(size_t)(t + 3) * Bb * 4096];
    }
    g_s2[b * 4096 + e] = (s0 + s1) + (s2 + s3);
}

// =====================================================================
// K4b: softmax over d + M = w1_right @ softmax.  grid: b=4
// =====================================================================
__global__ void k_chsoftmax_M(const float* __restrict__ w1) {
    __shared__ float s2s[64][65];
    int b = blockIdx.x;
    int tid = threadIdx.x;

    for (int e4 = tid; e4 < 1024; e4 += 256) {
        float4 v = *(const float4*)&g_s2[b * 4096 + e4 * 4];
        int e = e4 * 4, r = e >> 6, c = e & 63;
        s2s[r][c] = v.x; s2s[r][c + 1] = v.y; s2s[r][c + 2] = v.z; s2s[r][c + 3] = v.w;
    }
    __syncthreads();

    int w = tid >> 5, lane = tid & 31;
    for (int r = w; r < 64; r += 8) {
        float v0 = s2s[r][lane];
        float v1 = s2s[r][lane + 32];
        float m = fmaxf(v0, v1);
        #pragma unroll
        for (int off = 16; off; off >>= 1)
            m = fmaxf(m, __shfl_xor_sync(0xffffffffu, m, off));
        float e0 = __expf(v0 - m), e1 = __expf(v1 - m);
        float s = e0 + e1;
        #pragma unroll
        for (int off = 16; off; off >>= 1)
            s += __shfl_xor_sync(0xffffffffu, s, off);
        float inv = 1.f / s;
        s2s[r][lane] = e0 * inv;
        s2s[r][lane + 32] = e1 * inv;
    }
    __syncthreads();

    int tx = tid & 15, ty = tid >> 4;
    float acc[4][4] = {};
    #pragma unroll 4
    for (int c = 0; c < 64; c++) {
        float wv[4], qv[4];
        #pragma unroll
        for (int i = 0; i < 4; i++) wv[i] = w1[(ty * 4 + i) * 128 + 64 + c];
        #pragma unroll
        for (int j = 0; j < 4; j++) qv[j] = s2s[c][tx * 4 + j];
        #pragma unroll
        for (int i = 0; i < 4; i++)
            #pragma unroll
            for (int j = 0; j < 4; j++)
                acc[i][j] += wv[i] * qv[j];
    }
    #pragma unroll
    for (int i = 0; i < 4; i++)
        #pragma unroll
        for (int j = 0; j < 4; j++)
            g_M[b * 4096 + (ty * 4 + i) * 64 + tx * 4 + j] = acc[i][j];
}

// =====================================================================
// K5: y = w1_left @ combine(o1 splits) + M @ v + b1
// =====================================================================
__global__ void k_proj(const float* __restrict__ w1, const float* __restrict__ b1) {
    __shared__ float As[64][68];
    __shared__ float Ws[64][65];
    __shared__ float cS[NSPLIT][64];
    int b  = blockIdx.y;
    int p0 = blockIdx.x * 64;
    int tid = threadIdx.x;
    int tx = tid & 15, ty = tid >> 4;
    float acc[4][4] = {};

    if (tid < 64) {
        int row = p0 + tid;
        float2 mlv[NSPLIT];
        float m = -1e30f;
        #pragma unroll
        for (int s = 0; s < NSPLIT; s++) {
            mlv[s] = *(const float2*)&g_ml[((size_t)(s * Bb + b) * NN + row) * 2];
            m = fmaxf(m, mlv[s].x);
        }
        float den = 0.f, co[NSPLIT];
        #pragma unroll
        for (int s = 0; s < NSPLIT; s++) {
            co[s] = ex2(mlv[s].x - m);
            den += co[s] * mlv[s].y;
        }
        float inv = 1.f / den;
        #pragma unroll
        for (int s = 0; s < NSPLIT; s++) cS[s][tid] = co[s] * inv;
    }

    for (int ph = 0; ph < 2; ph++) {
        __syncthreads();
        int cg = tid & 15, r0 = tid >> 4;
        if (ph == 0) {
            for (int rr = r0; rr < 64; rr += 16) {
                float s0 = 0.f, s1 = 0.f, s2 = 0.f, s3 = 0.f;
                #pragma unroll
                for (int s = 0; s < NSPLIT; s++) {
                    float4 o = *(const float4*)&g_o1p[((size_t)(s * Bb + b) * NN + p0 + rr) * 64 + cg * 4];
                    float cf = cS[s][rr];
                    s0 += cf * o.x; s1 += cf * o.y; s2 += cf * o.z; s3 += cf * o.w;
                }
                *(float4*)&As[rr][cg * 4] = make_float4(s0, s1, s2, s3);
                float4 wv = *(const float4*)&w1[rr * 128 + cg * 4];
                Ws[rr][cg * 4 + 0] = wv.x; Ws[rr][cg * 4 + 1] = wv.y;
                Ws[rr][cg * 4 + 2] = wv.z; Ws[rr][cg * 4 + 3] = wv.w;
            }
        } else {
            for (int idx = tid; idx < 2048; idx += 256) {
                int ch = idx >> 5, p = idx & 31;
                unsigned val = g_vtw[(size_t)(b * 64 + ch) * (NN / 2) + blockIdx.x * 32 + p];
                __nv_bfloat162 h = *reinterpret_cast<__nv_bfloat162*>(&val);
                As[2 * p][ch]     = __bfloat162float(h.x);
                As[2 * p + 1][ch] = __bfloat162float(h.y);
            }
            for (int rr = r0; rr < 64; rr += 16) {
                float4 wv = *(const float4*)&g_M[b * 4096 + rr * 64 + cg * 4];
                Ws[rr][cg * 4 + 0] = wv.x; Ws[rr][cg * 4 + 1] = wv.y;
                Ws[rr][cg * 4 + 2] = wv.z; Ws[rr][cg * 4 + 3] = wv.w;
            }
        }
        __syncthreads();
        #pragma unroll 8
        for (int c = 0; c < 64; c++) {
            float a[4], wv[4];
            #pragma unroll
            for (int i = 0; i < 4; i++) a[i]  = As[ty * 4 + i][c];
            #pragma unroll
            for (int j = 0; j < 4; j++) wv[j] = Ws[tx * 4 + j][c];
            #pragma unroll
            for (int i = 0; i < 4; i++)
                #pragma unroll
                for (int j = 0; j < 4; j++)
                    acc[i][j] += a[i] * wv[j];
        }
    }
    #pragma unroll
    for (int i = 0; i < 4; i++) {
        float4 o;
        o.x = acc[i][0] + b1[tx * 4 + 0];
        o.y = acc[i][1] + b1[tx * 4 + 1];
        o.z = acc[i][2] + b1[tx * 4 + 2];
        o.w = acc[i][3] + b1[tx * 4 + 3];
        *(float4*)&g_y[(size_t)(b * NN + p0 + ty * 4 + i) * 64 + tx * 4] = o;
    }
}

// =====================================================================
// K6: bilinear 2x upsample + residual, coalesced.
// grid (128, Bb), block 256
// =====================================================================
__global__ void k_upsample2(const float* __restrict__ x, float* __restrict__ out) {
    __shared__ float Y[2][64 * 66];
    int b = blockIdx.y, i = blockIdx.x;
    int tid = threadIdx.x;
    int p = i >> 1;
    int r0, r1; float wy0, wy1;
    if (i & 1) { r0 = p; r1 = (p + 1 < 64) ? p + 1 : 63; wy0 = 0.75f; wy1 = 0.25f; }
    else       { r0 = (p > 0) ? p - 1 : 0; r1 = p;       wy0 = 0.25f; wy1 = 0.75f; }

    const float* yb = g_y + (size_t)b * NN * 64;
    int rows[2] = {r0, r1};
    for (int e2 = tid; e2 < 4096; e2 += 256) {
        int rr  = e2 >> 11;
        int rem = e2 & 2047;
        int s   = rem >> 5;
        int c2  = rem & 31;
        float2 v = *(const float2*)&yb[((rows[rr] * 64 + s) * 64) + c2 * 2];
        *(float2*)&Y[rr][s * 66 + c2 * 2] = v;
    }
    __syncthreads();

    size_t obase = ((size_t)b * 64 * 128 + i) * 128;
    for (int e = tid; e < 8192; e += 256) {
        int c = e >> 7, j = e & 127;
        int q = j >> 1;
        int s0, s1; float wx0, wx1;
        if (j & 1) { s0 = q; s1 = (q + 1 < 64) ? q + 1 : 63; wx0 = 0.75f; wx1 = 0.25f; }
        else       { s0 = (q > 0) ? q - 1 : 0; s1 = q;       wx0 = 0.25f; wx1 = 0.75f; }
        float v = wy0 * (wx0 * Y[0][s0 * 66 + c] + wx1 * Y[0][s1 * 66 + c])
                + wy1 * (wx0 * Y[1][s0 * 66 + c] + wx1 * Y[1][s1 * 66 + c]);
        size_t oi = obase + (size_t)c * 16384 + j;
        out[oi] = v + x[oi];
    }
}

// =====================================================================
extern "C" void kernel_launch(void* const* d_in, const int* in_sizes, int n_in,
                              void* d_out, int out_size) {
    const float* x        = (const float*)d_in[0];
    const float* pm_gamma = (const float*)d_in[1];
    const float* pm_beta  = (const float*)d_in[2];
    const float* pm_w     = (const float*)d_in[3];
    const float* pm_b     = (const float*)d_in[4];
    const float* w2 = (const float*)d_in[5];
    const float* b2 = (const float*)d_in[6];
    const float* w3 = (const float*)d_in[7];
    const float* b3 = (const float*)d_in[8];
    const float* w4 = (const float*)d_in[9];
    const float* b4 = (const float*)d_in[10];
    const float* w5 = (const float*)d_in[11];
    const float* b5 = (const float*)d_in[12];
    const float* w6 = (const float*)d_in[13];
    const float* b6 = (const float*)d_in[14];
    const float* w1 = (const float*)d_in[15];
    const float* b1 = (const float*)d_in[16];
    float* out = (float*)d_out;

    const int merge_smem = (64 * 260 + 64 * 68) * 4;                  // 83968 B
    const int qkv_smem   = (64 * 68 + 64 * 68 + 64 * 65) * 4;         // 51456 B
    const int attn_smem  = (2 * 64 * SKW * 2 + 4 * 32 * SPW) * 4;     // 55296 B
    cudaFuncSetAttribute(k_merge_pml, cudaFuncAttributeMaxDynamicSharedMemorySize, merge_smem);
    cudaFuncSetAttribute(k_qkv5,      cudaFuncAttributeMaxDynamicSharedMemorySize, qkv_smem);
    cudaFuncSetAttribute(k_attn1_tc,  cudaFuncAttributeMaxDynamicSharedMemorySize, attn_smem);

    k_merge_pml  <<<dim3(64, Bb), 256, merge_smem>>>(x, pm_gamma, pm_beta, pm_w, pm_b);
    k_qkv5       <<<dim3(64, Bb), 256, qkv_smem>>>(w2, b2, w3, b3, w4, b4, w5, b5, w6, b6);
    k_sreduce    <<<dim3(16, Bb), 256>>>();
    k_attn1_tc   <<<dim3(32, Bb, NSPLIT), 128, attn_smem>>>();
    k_chsoftmax_M<<<Bb, 256>>>(w1);
    k_proj       <<<dim3(64, Bb), 256>>>(w1, b1);
    k_upsample2  <<<dim3(128, Bb), 256>>>(x, out);
}